// round 12
// baseline (speedup 1.0000x reference)
#include <cuda_runtime.h>
#include <cuda_fp16.h>
#include <math.h>
#include <stdint.h>

#define TT 8192
#define DD 256
#define FF 1024
#define EE 32
#define KK 4
#define TM 128            // tokens per tile (MMA M)
#define FC 64             // ffn chunk
#define NCH (FF / FC)     // 16

// packed-weight block geometry (halves)
#define SLICE_H  9216     // [2 mat][64 f][72]
#define QUART_H  4608     // [64 d][72]
#define APART_H  (4 * SLICE_H)            // 36864
#define CHUNK_H  (APART_H + 4 * QUART_H)  // 55296
#define NBLK     (EE * NCH)               // 512

// ---------------- scratch globals ----------------
__device__ int   g_counts[EE];
__device__ int   g_offsets[EE + 1];
__device__ float g_probs_sum[EE];
__device__ int   g_as_e[TT * KK];
__device__ int   g_as_pos[TT * KK];
__device__ float g_as_w[TT * KK];
__device__ int   g_list_tok[TT * KK];
__device__ float g_list_w[TT * KK];
__device__ int   g_slot[TT * KK];
__device__ int   g_tile_e[2048];
__device__ int   g_tile_m0[2048];
__device__ int   g_ntiles;
__device__ float g_scratch[(size_t)TT * KK * DD];       // 32 MB partials
__device__ __half g_xh[(size_t)TT * DD];                // 4 MB fp16 x
__device__ __half g_wpack[(size_t)NBLK * CHUNK_H];      // 56.6 MB packed weights

// ---------------- PTX helpers ----------------
__device__ __forceinline__ void mma16(float* c, const uint32_t* a, uint32_t b0, uint32_t b1) {
    asm("mma.sync.aligned.m16n8k16.row.col.f32.f16.f16.f32 "
        "{%0,%1,%2,%3},{%4,%5,%6,%7},{%8,%9},{%0,%1,%2,%3};"
        : "+f"(c[0]), "+f"(c[1]), "+f"(c[2]), "+f"(c[3])
        : "r"(a[0]), "r"(a[1]), "r"(a[2]), "r"(a[3]), "r"(b0), "r"(b1));
}
__device__ __forceinline__ void ldm4(uint32_t* r, uint32_t addr) {
    asm volatile("ldmatrix.sync.aligned.m8n8.x4.shared.b16 {%0,%1,%2,%3}, [%4];"
        : "=r"(r[0]), "=r"(r[1]), "=r"(r[2]), "=r"(r[3]) : "r"(addr));
}
__device__ __forceinline__ void cp16z(uint32_t dst, const void* src, int ssz) {
    asm volatile("cp.async.cg.shared.global [%0], [%1], 16, %2;" :: "r"(dst), "l"(src), "r"(ssz));
}
#define CP_COMMIT() asm volatile("cp.async.commit_group;" ::: "memory")
#define CP_WAIT0()  asm volatile("cp.async.wait_group 0;" ::: "memory")

__device__ __forceinline__ void bulk_g2s(uint32_t dst, const void* src, uint32_t bytes,
                                         uint32_t mbar) {
    asm volatile("cp.async.bulk.shared::cta.global.mbarrier::complete_tx::bytes "
                 "[%0], [%1], %2, [%3];"
                 :: "r"(dst), "l"(src), "r"(bytes), "r"(mbar) : "memory");
}
#define MBARRIER_INIT(a, n) \
    asm volatile("mbarrier.init.shared.b64 [%0], %1;" :: "r"((uint32_t)(a)), "r"((uint32_t)(n)) : "memory")
#define MBARRIER_EXPECT_TX(a, b) \
    asm volatile("mbarrier.arrive.expect_tx.shared.b64 _, [%0], %1;" :: "r"((uint32_t)(a)), "r"((uint32_t)(b)) : "memory")
#define MBAR_WAIT(a, ph) do {                                                        \
    uint32_t _m = (uint32_t)(a); uint32_t _p = (uint32_t)(ph); uint32_t _d;          \
    asm volatile("{\n\t.reg .pred p;\n\t"                                            \
        "mbarrier.try_wait.parity.acquire.cta.shared::cta.b64 p, [%1], %2;\n\t"      \
        "selp.b32 %0, 1, 0, p;\n\t}"                                                 \
        : "=r"(_d) : "r"(_m), "r"(_p) : "memory");                                   \
    if (!_d) {                                                                        \
        asm volatile("{\n\t.reg .pred P1;\n\t"                                       \
            "WL_%=:\n\t"                                                             \
            "mbarrier.try_wait.parity.acquire.cta.shared::cta.b64 P1, [%0], %1, 0x989680;\n\t" \
            "@P1 bra.uni WD_%=;\n\t"                                                 \
            "bra.uni WL_%=;\n\t"                                                     \
            "WD_%=:\n\t}"                                                            \
            :: "r"(_m), "r"(_p) : "memory");                                         \
    } } while (0)

__device__ __forceinline__ uint32_t smem_u32(const void* p) {
    uint32_t a;
    asm("{ .reg .u64 t; cvta.to.shared.u64 t, %1; cvt.u32.u64 %0, t; }" : "=r"(a) : "l"(p));
    return a;
}

// FFMA-only sigmoid (no MUFU)
__device__ __forceinline__ float fast_sigmoid(float x) {
    float t = -1.442695041f * x;
    float fn = rintf(t);
    int   n  = (int)fn;
    float f  = t - fn;
    float p = 0.0013333558f;
    p = fmaf(p, f, 0.0096181291f);
    p = fmaf(p, f, 0.0555041087f);
    p = fmaf(p, f, 0.2402265069f);
    p = fmaf(p, f, 0.6931471806f);
    p = fmaf(p, f, 1.0f);
    float e = __int_as_float(__float_as_int(p) + (n << 23));
    float d = 1.0f + e;
    float r = __int_as_float(0x7EF311C3 - __float_as_int(d));
    r = r * (2.0f - d * r);
    r = r * (2.0f - d * r);
    r = r * (2.0f - d * r);
    return r;
}

// ---------------- init ----------------
__global__ void init_kernel()
{
    int i = threadIdx.x;
    if (i < EE) { g_counts[i] = 0; g_probs_sum[i] = 0.f; }
}

// ---------------- x fp32 -> fp16 ----------------
__global__ __launch_bounds__(256) void conv_x_kernel(const float* __restrict__ src)
{
    int i = blockIdx.x * 256 + threadIdx.x;   // TT*DD/8 items
    float4 a = ((const float4*)src)[2 * i];
    float4 b = ((const float4*)src)[2 * i + 1];
    __half2 h0 = __floats2half2_rn(a.x, a.y);
    __half2 h1 = __floats2half2_rn(a.z, a.w);
    __half2 h2 = __floats2half2_rn(b.x, b.y);
    __half2 h3 = __floats2half2_rn(b.z, b.w);
    uint4 o;
    o.x = *(uint32_t*)&h0; o.y = *(uint32_t*)&h1;
    o.z = *(uint32_t*)&h2; o.w = *(uint32_t*)&h3;
    ((uint4*)g_xh)[i] = o;
}

// ---------------- pack Wg/Wu into SMEM-image layout ----------------
__global__ __launch_bounds__(256) void pack_a_kernel(const float* __restrict__ wg,
                                                     const float* __restrict__ wu)
{
    int idx = blockIdx.x * 256 + threadIdx.x;    // NBLK*4096 items (8 halves each)
    int blk = idx >> 12;
    int rem = idx & 4095;
    int ks  = rem >> 10;
    int mat = (rem >> 9) & 1;
    int f   = (rem >> 3) & 63;
    int k8  = rem & 7;
    int e = blk >> 4, c = blk & 15;
    const float* src = (mat ? wu : wg)
        + (((size_t)e * FF + (size_t)c * FC + f) * DD + ks * 64 + k8 * 8);
    float4 a = ((const float4*)src)[0];
    float4 b = ((const float4*)src)[1];
    __half2 h0 = __floats2half2_rn(a.x, a.y);
    __half2 h1 = __floats2half2_rn(a.z, a.w);
    __half2 h2 = __floats2half2_rn(b.x, b.y);
    __half2 h3 = __floats2half2_rn(b.z, b.w);
    uint4 o;
    o.x = *(uint32_t*)&h0; o.y = *(uint32_t*)&h1;
    o.z = *(uint32_t*)&h2; o.w = *(uint32_t*)&h3;
    __half* dst = g_wpack + ((size_t)blk * CHUNK_H + ks * SLICE_H + mat * (SLICE_H / 2)
                             + f * 72 + k8 * 8);
    *(uint4*)dst = o;
}

// ---------------- pack Wd ----------------
__global__ __launch_bounds__(256) void pack_b_kernel(const float* __restrict__ wd)
{
    int idx = blockIdx.x * 256 + threadIdx.x;    // NBLK*2048 items
    int blk = idx >> 11;
    int rem = idx & 2047;
    int q   = rem >> 9;
    int d   = (rem >> 3) & 63;
    int f8  = rem & 7;
    int e = blk >> 4, c = blk & 15;
    const float* src = wd + (((size_t)e * DD + q * 64 + d) * FF + (size_t)c * FC + f8 * 8);
    float4 a = ((const float4*)src)[0];
    float4 b = ((const float4*)src)[1];
    __half2 h0 = __floats2half2_rn(a.x, a.y);
    __half2 h1 = __floats2half2_rn(a.z, a.w);
    __half2 h2 = __floats2half2_rn(b.x, b.y);
    __half2 h3 = __floats2half2_rn(b.z, b.w);
    uint4 o;
    o.x = *(uint32_t*)&h0; o.y = *(uint32_t*)&h1;
    o.z = *(uint32_t*)&h2; o.w = *(uint32_t*)&h3;
    __half* dst = g_wpack + ((size_t)blk * CHUNK_H + APART_H + q * QUART_H
                             + d * 72 + f8 * 8);
    *(uint4*)dst = o;
}

// ---------------- router (known-good) ----------------
__global__ __launch_bounds__(256) void router_kernel(const float* __restrict__ x,
                                                     const float* __restrict__ rw)
{
    __shared__ float rw_s[EE * 257];
    __shared__ float xsh[8 * 260];
    __shared__ float pacc[EE];

    const int tid  = threadIdx.x;
    const int lane = tid & 31;
    const int warp = tid >> 5;

    for (int i = tid; i < EE * DD; i += 256) {
        int e = i >> 8, d = i & 255;
        rw_s[e * 257 + d] = rw[i];
    }
    if (tid < EE) pacc[tid] = 0.f;
    __syncthreads();

    const int t = blockIdx.x * 8 + warp;
    {
        const float4* xr = (const float4*)(x + (size_t)t * DD);
        float4 a = xr[lane * 2];
        float4 b = xr[lane * 2 + 1];
        *(float4*)&xsh[warp * 260 + lane * 8]     = a;
        *(float4*)&xsh[warp * 260 + lane * 8 + 4] = b;
    }
    __syncwarp();

    float acc = 0.f;
    const float* xrow  = &xsh[warp * 260];
    const float* rwrow = &rw_s[lane * 257];
#pragma unroll 8
    for (int d = 0; d < DD; d++) acc = fmaf(xrow[d], rwrow[d], acc);
    const float logit = acc;

    float m = logit;
#pragma unroll
    for (int o = 16; o; o >>= 1) m = fmaxf(m, __shfl_xor_sync(0xffffffffu, m, o));
    float p = expf(logit - m);
    float s = p;
#pragma unroll
    for (int o = 16; o; o >>= 1) s += __shfl_xor_sync(0xffffffffu, s, o);
    atomicAdd(&pacc[lane], p / s);

    float lv = logit;
    float vals[KK]; int idxs[KK];
#pragma unroll
    for (int k = 0; k < KK; k++) {
        float v = lv; int id = lane;
#pragma unroll
        for (int o = 16; o; o >>= 1) {
            float v2 = __shfl_xor_sync(0xffffffffu, v, o);
            int   i2 = __shfl_xor_sync(0xffffffffu, id, o);
            if (v2 > v || (v2 == v && i2 < id)) { v = v2; id = i2; }
        }
        vals[k] = v; idxs[k] = id;
        if (lane == id) lv = __int_as_float(0xff800000);
    }

    float ws[KK]; float sum = 0.f;
#pragma unroll
    for (int k = 0; k < KK; k++) { ws[k] = expf(vals[k] - vals[0]); sum += ws[k]; }
    const float inv = 1.f / sum;

    if (lane == 0) {
#pragma unroll
        for (int k = 0; k < KK; k++) {
            int e   = idxs[k];
            int pos = atomicAdd(&g_counts[e], 1);
            int a   = t * KK + k;
            g_as_e[a] = e; g_as_pos[a] = pos; g_as_w[a] = ws[k] * inv;
        }
    }
    __syncthreads();
    if (tid < EE) atomicAdd(&g_probs_sum[tid], pacc[tid]);
}

// ---------------- scan offsets + aux loss + tile list ----------------
__global__ void scan_aux_kernel(float* __restrict__ out, int out_size)
{
    const int tid = threadIdx.x;   // 32 threads
    int c = g_counts[tid];
    int v = c;
#pragma unroll
    for (int o = 1; o < 32; o <<= 1) {
        int n = __shfl_up_sync(0xffffffffu, v, o);
        if (tid >= o) v += n;
    }
    g_offsets[tid] = v - c;
    if (tid == 31) g_offsets[EE] = v;

    int nt = (c + TM - 1) / TM;
    int tv = nt;
#pragma unroll
    for (int o = 1; o < 32; o <<= 1) {
        int n = __shfl_up_sync(0xffffffffu, tv, o);
        if (tid >= o) tv += n;
    }
    int tb = tv - nt;
    for (int j = 0; j < nt; j++) { g_tile_e[tb + j] = tid; g_tile_m0[tb + j] = j * TM; }
    if (tid == 31) g_ntiles = tv;

    const float invT = 1.f / (float)TT;
    float part = ((float)c * invT) * (g_probs_sum[tid] * invT);
#pragma unroll
    for (int o = 16; o; o >>= 1) part += __shfl_xor_sync(0xffffffffu, part, o);
    if (tid == 0 && out_size > TT * DD) out[(size_t)TT * DD] = (float)EE * part;
}

// ---------------- per-expert token lists + slot map ----------------
__global__ void fill_kernel()
{
    int i = blockIdx.x * blockDim.x + threadIdx.x;
    if (i < TT * KK) {
        int e    = g_as_e[i];
        int slot = g_offsets[e] + g_as_pos[i];
        g_list_tok[slot] = i >> 2;
        g_list_w[slot]   = g_as_w[i];
        g_slot[i]        = slot;
    }
}

// ---------------- fp16 mma.sync fused expert FFN, bulk-copy staging ----------------
// SMEM layout (halves):
//   Xs  [128][264]   @ 0       (33792 h)
//   hS  [128][72]    @ 33792   (9216 h)
//   WA  [2][9216]    @ 43008   (18432 h)   Phase A slices, double buffered
//   WB  [2][4608]    @ 61440   (9216 h)    Phase B quarters, double buffered
//   mbars @ 70656h (4 x 8B), toks @ 70688h, wsh after
constexpr int XS_STRIDE = 264;
constexpr int HS_STRIDE = 72;
constexpr int OFF_H    = 33792;
constexpr int OFF_WA   = 43008;
constexpr int OFF_WB   = 61440;
constexpr int OFF_MB   = 70656;
constexpr int OFF_TOK  = 70688;
constexpr int EXP_SMEM = (OFF_TOK + 512) * 2;   // 142400 B

__global__ __launch_bounds__(256, 1)
void moe_mma_kernel()
{
    extern __shared__ __half sm[];
    __half* Xs = sm;
    __half* hS = sm + OFF_H;
    int*   toks = (int*)(sm + OFF_TOK);
    float* wsh  = (float*)(toks + 128);

    const uint32_t xs_b = smem_u32(Xs);
    const uint32_t hs_b = smem_u32(hS);
    const uint32_t wa_b = smem_u32(sm + OFF_WA);
    const uint32_t wb_b = smem_u32(sm + OFF_WB);
    const uint32_t mb   = smem_u32(sm + OFF_MB);

    const int tid  = threadIdx.x;
    const int lane = tid & 31;
    const int warp = tid >> 5;
    const int lq   = lane & 3;
    const int lh   = lane >> 2;
    const int wm   = warp & 3;        // M tile (32 rows each)
    const int wn   = warp >> 2;       // N tile (32 cols each)

    const int l7  = lane & 7;
    const int l8  = (lane >> 3) & 1;
    const int l16 = (lane >> 4) & 1;

    const int rowA0 = wm * 32 + l7 + 8 * l8;
    const int rowB0 = wn * 32 + l7 + 8 * l8;

    const uint32_t aX = xs_b + (uint32_t)((rowA0 * XS_STRIDE + l16 * 8) * 2);
    const uint32_t aH = hs_b + (uint32_t)((rowA0 * HS_STRIDE + l16 * 8) * 2);
    const uint32_t bW = (uint32_t)((rowB0 * HS_STRIDE + l16 * 8) * 2);

    if (tid == 0) {
        MBARRIER_INIT(mb + 0,  1);  MBARRIER_INIT(mb + 8,  1);   // A bufs
        MBARRIER_INIT(mb + 16, 1);  MBARRIER_INIT(mb + 24, 1);   // B bufs
    }
    __syncthreads();

    int phA[2] = {0, 0};
    int phB[2] = {0, 0};

    const int ntiles = g_ntiles;

    for (int tile = blockIdx.x; tile < ntiles; tile += gridDim.x) {
        const int e     = g_tile_e[tile];
        const int m0    = g_tile_m0[tile];
        const int base  = g_offsets[e];
        const int count = g_offsets[e + 1] - base;

        if (tid < TM) {
            int r = m0 + tid;
            bool v = r < count;
            toks[tid] = v ? g_list_tok[base + r] : -1;
            wsh[tid]  = v ? g_list_w[base + r] : 0.f;
        }
        __syncthreads();

        // ---- stage X fp16 (cp.async; once per tile) ----
#pragma unroll 4
        for (int j = 0; j < 16; j++) {
            int idx = tid + j * 256;
            int r = idx >> 5, c8 = idx & 31;
            int t = toks[r];
            uint32_t dst = xs_b + (uint32_t)((r * XS_STRIDE + c8 * 8) * 2);
            const __half* src = g_xh + ((size_t)(t < 0 ? 0 : t) * DD + c8 * 8);
            cp16z(dst, src, t < 0 ? 0 : 16);
        }
        CP_COMMIT();

        const __half* wblk = g_wpack + (size_t)(e * NCH) * CHUNK_H;

        float acc[4][2][4][4];
#pragma unroll
        for (int q = 0; q < 4; q++)
#pragma unroll
            for (int mt = 0; mt < 2; mt++)
#pragma unroll
                for (int nt = 0; nt < 4; nt++)
#pragma unroll
                    for (int r = 0; r < 4; r++) acc[q][mt][nt][r] = 0.f;

        CP_WAIT0();
        __syncthreads();   // X visible; W bufs free

        for (int c = 0; c < NCH; c++) {
            const __half* wch = wblk + (size_t)c * CHUNK_H;

            // ======== Phase A (fused G+U): 4 k-slices of 64 ========
            float cG[2][4][4], cU[2][4][4];
#pragma unroll
            for (int mt = 0; mt < 2; mt++)
#pragma unroll
                for (int nt = 0; nt < 4; nt++)
#pragma unroll
                    for (int r = 0; r < 4; r++) { cG[mt][nt][r] = 0.f; cU[mt][nt][r] = 0.f; }

            if (tid == 0) {   // slice 0 -> buf 0
                MBARRIER_EXPECT_TX(mb + 0, SLICE_H * 2);
                bulk_g2s(wa_b, wch, SLICE_H * 2, mb + 0);
            }
#pragma unroll 1
            for (int ks = 0; ks < 4; ks++) {
                const int buf = ks & 1;
                if (ks < 3 && tid == 0) {
                    const int nb = (ks + 1) & 1;
                    MBARRIER_EXPECT_TX(mb + nb * 8, SLICE_H * 2);
                    bulk_g2s(wa_b + nb * (SLICE_H * 2),
                             wch + (size_t)(ks + 1) * SLICE_H, SLICE_H * 2, mb + nb * 8);
                }
                MBAR_WAIT(mb + buf * 8, phA[buf]); phA[buf] ^= 1;
                const uint32_t wsbB = wa_b + (uint32_t)(buf * SLICE_H * 2);
                const int d0 = ks * 64;
#pragma unroll
                for (int kk = 0; kk < 4; kk++) {
                    uint32_t a[2][4];
#pragma unroll
                    for (int mt = 0; mt < 2; mt++)
                        ldm4(a[mt], aX + (uint32_t)(((mt * 16 * XS_STRIDE) + d0 + kk * 16) * 2));
                    uint32_t bg[8], bu[8];
#pragma unroll
                    for (int nt2 = 0; nt2 < 2; nt2++) {
                        ldm4(bg + nt2 * 4, wsbB + bW + (uint32_t)(((nt2 * 16 * HS_STRIDE) + kk * 16) * 2));
                        ldm4(bu + nt2 * 4, wsbB + bW + (uint32_t)(((4608 + nt2 * 16 * HS_STRIDE) + kk * 16) * 2));
                    }
#pragma unroll
                    for (int mt = 0; mt < 2; mt++)
#pragma unroll
                        for (int nt = 0; nt < 4; nt++) {
                            int nt2 = nt >> 1, hi = nt & 1;
                            mma16(cG[mt][nt], a[mt], bg[nt2 * 4 + hi], bg[nt2 * 4 + 2 + hi]);
                            mma16(cU[mt][nt], a[mt], bu[nt2 * 4 + hi], bu[nt2 * 4 + 2 + hi]);
                        }
                }
                __syncthreads();   // all warps done with this buf
            }

            // Phase B prologue: quarter 0 -> buf 0 (overlaps silu)
            if (tid == 0) {
                MBARRIER_EXPECT_TX(mb + 16, QUART_H * 2);
                bulk_g2s(wb_b, wch + APART_H, QUART_H * 2, mb + 16);
            }

            // ---- h = silu(G) * U -> hS (fp16) ----
#pragma unroll
            for (int mt = 0; mt < 2; mt++)
#pragma unroll
                for (int nt = 0; nt < 4; nt++) {
                    int col = wn * 32 + nt * 8 + 2 * lq;
#pragma unroll
                    for (int hf = 0; hf < 2; hf++) {
                        int row = wm * 32 + mt * 16 + hf * 8 + lh;
                        float g0 = cG[mt][nt][hf * 2 + 0];
                        float g1 = cG[mt][nt][hf * 2 + 1];
                        float h0 = g0 * fast_sigmoid(g0) * cU[mt][nt][hf * 2 + 0];
                        float h1 = g1 * fast_sigmoid(g1) * cU[mt][nt][hf * 2 + 1];
                        __half2 o2 = __floats2half2_rn(h0, h1);
                        *(__half2*)&hS[row * HS_STRIDE + col] = o2;
                    }
                }
            __syncthreads();   // hS visible to all warps

            // ======== Phase B: out += h @ Wd^T (4 quarters of D) ========
#pragma unroll 1
            for (int q = 0; q < 4; q++) {
                const int buf = q & 1;
                if (q < 3 && tid == 0) {
                    const int nb = (q + 1) & 1;
                    MBARRIER_EXPECT_TX(mb + 16 + nb * 8, QUART_H * 2);
                    bulk_g2s(wb_b + nb * (QUART_H * 2),
                             wch + APART_H + (size_t)(q + 1) * QUART_H, QUART_H * 2,
                             mb + 16 + nb * 8);
                }
                MBAR_WAIT(mb + 16 + buf * 8, phB[buf]); phB[buf] ^= 1;
                const uint32_t wdbB = wb_b + (uint32_t)(buf * QUART_H * 2);
#pragma unroll
                for (int kk = 0; kk < 4; kk++) {
                    uint32_t a[2][4];
#pragma unroll
                    for (int mt = 0; mt < 2; mt++)
                        ldm4(a[mt], aH + (uint32_t)(((mt * 16 * HS_STRIDE) + kk * 16) * 2));
                    uint32_t bbr[8];
#pragma unroll
                    for (int nt2 = 0; nt2 < 2; nt2++)
                        ldm4(bbr + nt2 * 4, wdbB + bW + (uint32_t)(((nt2 * 16 * HS_STRIDE) + kk * 16) * 2));
#pragma unroll
                    for (int mt = 0; mt < 2; mt++)
#pragma unroll
                        for (int nt = 0; nt < 4; nt++) {
                            int nt2 = nt >> 1, hi = nt & 1;
                            mma16(acc[q][mt][nt], a[mt], bbr[nt2 * 4 + hi], bbr[nt2 * 4 + 2 + hi]);
                        }
                }
                __syncthreads();   // buf free; (q==3) hS free for next chunk
            }
        }

        // ---- epilogue: weighted write to scratch ----
#pragma unroll
        for (int q = 0; q < 4; q++)
#pragma unroll
            for (int mt = 0; mt < 2; mt++)
#pragma unroll
                for (int hf = 0; hf < 2; hf++) {
                    int tr = wm * 32 + mt * 16 + hf * 8 + lh;
                    if (m0 + tr < count) {
                        float w = wsh[tr];
                        float* dst = g_scratch + (size_t)(base + m0 + tr) * DD
                                   + q * 64 + wn * 32 + 2 * lq;
#pragma unroll
                        for (int nt = 0; nt < 4; nt++) {
                            float2 v;
                            v.x = acc[q][mt][nt][hf * 2 + 0] * w;
                            v.y = acc[q][mt][nt][hf * 2 + 1] * w;
                            *(float2*)(dst + nt * 8) = v;
                        }
                    }
                }
        __syncthreads();   // protect toks/wsh/Xs before next tile
    }
}

// ---------------- combine: out[t] = sum of token's 4 weighted slots ----------------
__global__ __launch_bounds__(256) void combine_kernel(float* __restrict__ out)
{
    int idx = blockIdx.x * 256 + threadIdx.x;     // TT*64 float4 items
    int t = idx >> 6, q = (idx & 63) * 4;
    const int* sl = g_slot + t * 4;
    float4 a = *(const float4*)(g_scratch + (size_t)sl[0] * DD + q);
    float4 b = *(const float4*)(g_scratch + (size_t)sl[1] * DD + q);
    float4 c = *(const float4*)(g_scratch + (size_t)sl[2] * DD + q);
    float4 d = *(const float4*)(g_scratch + (size_t)sl[3] * DD + q);
    float4 r;
    r.x = a.x + b.x + c.x + d.x;
    r.y = a.y + b.y + c.y + d.y;
    r.z = a.z + b.z + c.z + d.z;
    r.w = a.w + b.w + c.w + d.w;
    *(float4*)(out + (size_t)t * DD + q) = r;
}

// ---------------- launch ----------------
extern "C" void kernel_launch(void* const* d_in, const int* in_sizes, int n_in,
                              void* d_out, int out_size)
{
    const float* x  = (const float*)d_in[0];
    const float* rw = (const float*)d_in[1];
    const float* wg = (const float*)d_in[2];
    const float* wu = (const float*)d_in[3];
    const float* wd = (const float*)d_in[4];
    float* out = (float*)d_out;

    cudaMemsetAsync(d_out, 0, (size_t)out_size * sizeof(float));
    init_kernel<<<1, 32>>>();
    router_kernel<<<TT / 8, 256>>>(x, rw);
    scan_aux_kernel<<<1, 32>>>(out, out_size);
    fill_kernel<<<(TT * KK + 255) / 256, 256>>>();

    conv_x_kernel<<<TT * DD / 8 / 256, 256>>>(x);
    pack_a_kernel<<<NBLK * 4096 / 256, 256>>>(wg, wu);
    pack_b_kernel<<<NBLK * 2048 / 256, 256>>>(wd);

    cudaFuncSetAttribute(moe_mma_kernel,
                         cudaFuncAttributeMaxDynamicSharedMemorySize, EXP_SMEM);
    moe_mma_kernel<<<148, 256, EXP_SMEM>>>();
    combine_kernel<<<TT * 64 / 256, 256>>>(out);
}

// round 13
// speedup vs baseline: 1.1568x; 1.1568x over previous
#include <cuda_runtime.h>
#include <cuda_fp16.h>
#include <math.h>
#include <stdint.h>

#define TT 8192
#define DD 256
#define FF 1024
#define EE 32
#define KK 4
#define TM 128            // tokens per tile (MMA M)
#define FC 64             // ffn chunk
#define NCH (FF / FC)     // 16

// packed-weight block geometry (halves)
#define SLICE_H  9216     // [2 mat][64 f][72]
#define QUART_H  4608     // [64 d][72]
#define APART_H  (4 * SLICE_H)            // 36864
#define CHUNK_H  (APART_H + 4 * QUART_H)  // 55296
#define NBLK     (EE * NCH)               // 512

// ---------------- scratch globals ----------------
__device__ int   g_counts[EE];
__device__ int   g_offsets[EE + 1];
__device__ float g_probs_sum[EE];
__device__ int   g_as_e[TT * KK];
__device__ int   g_as_pos[TT * KK];
__device__ float g_as_w[TT * KK];
__device__ int   g_list_tok[TT * KK];
__device__ float g_list_w[TT * KK];
__device__ int   g_slot[TT * KK];
__device__ int   g_tile_e[2048];
__device__ int   g_tile_m0[2048];
__device__ int   g_ntiles;
__device__ float g_scratch[(size_t)TT * KK * DD];       // 32 MB partials
__device__ __half g_xh[(size_t)TT * DD];                // 4 MB fp16 x
__device__ __half g_wpack[(size_t)NBLK * CHUNK_H];      // 56.6 MB packed weights

// ---------------- PTX helpers ----------------
__device__ __forceinline__ void mma16(float* c, const uint32_t* a, uint32_t b0, uint32_t b1) {
    asm("mma.sync.aligned.m16n8k16.row.col.f32.f16.f16.f32 "
        "{%0,%1,%2,%3},{%4,%5,%6,%7},{%8,%9},{%0,%1,%2,%3};"
        : "+f"(c[0]), "+f"(c[1]), "+f"(c[2]), "+f"(c[3])
        : "r"(a[0]), "r"(a[1]), "r"(a[2]), "r"(a[3]), "r"(b0), "r"(b1));
}
__device__ __forceinline__ void ldm4(uint32_t* r, uint32_t addr) {
    asm volatile("ldmatrix.sync.aligned.m8n8.x4.shared.b16 {%0,%1,%2,%3}, [%4];"
        : "=r"(r[0]), "=r"(r[1]), "=r"(r[2]), "=r"(r[3]) : "r"(addr));
}
__device__ __forceinline__ void cp16z(uint32_t dst, const void* src, int ssz) {
    asm volatile("cp.async.cg.shared.global [%0], [%1], 16, %2;" :: "r"(dst), "l"(src), "r"(ssz));
}
#define CP_COMMIT() asm volatile("cp.async.commit_group;" ::: "memory")
#define CP_WAIT0()  asm volatile("cp.async.wait_group 0;" ::: "memory")

__device__ __forceinline__ void bulk_g2s(uint32_t dst, const void* src, uint32_t bytes,
                                         uint32_t mbar) {
    asm volatile("cp.async.bulk.shared::cta.global.mbarrier::complete_tx::bytes "
                 "[%0], [%1], %2, [%3];"
                 :: "r"(dst), "l"(src), "r"(bytes), "r"(mbar) : "memory");
}
#define MBARRIER_INIT(a, n) \
    asm volatile("mbarrier.init.shared.b64 [%0], %1;" :: "r"((uint32_t)(a)), "r"((uint32_t)(n)) : "memory")
#define MBARRIER_EXPECT_TX(a, b) \
    asm volatile("mbarrier.arrive.expect_tx.shared.b64 _, [%0], %1;" :: "r"((uint32_t)(a)), "r"((uint32_t)(b)) : "memory")
#define MBAR_WAIT(a, ph) do {                                                        \
    uint32_t _m = (uint32_t)(a); uint32_t _p = (uint32_t)(ph); uint32_t _d;          \
    asm volatile("{\n\t.reg .pred p;\n\t"                                            \
        "mbarrier.try_wait.parity.acquire.cta.shared::cta.b64 p, [%1], %2;\n\t"      \
        "selp.b32 %0, 1, 0, p;\n\t}"                                                 \
        : "=r"(_d) : "r"(_m), "r"(_p) : "memory");                                   \
    if (!_d) {                                                                        \
        asm volatile("{\n\t.reg .pred P1;\n\t"                                       \
            "WL_%=:\n\t"                                                             \
            "mbarrier.try_wait.parity.acquire.cta.shared::cta.b64 P1, [%0], %1, 0x989680;\n\t" \
            "@P1 bra.uni WD_%=;\n\t"                                                 \
            "bra.uni WL_%=;\n\t"                                                     \
            "WD_%=:\n\t}"                                                            \
            :: "r"(_m), "r"(_p) : "memory");                                         \
    } } while (0)

__device__ __forceinline__ uint32_t smem_u32(const void* p) {
    uint32_t a;
    asm("{ .reg .u64 t; cvta.to.shared.u64 t, %1; cvt.u32.u64 %0, t; }" : "=r"(a) : "l"(p));
    return a;
}

// ---------------- init ----------------
__global__ void init_kernel()
{
    int i = threadIdx.x;
    if (i < EE) { g_counts[i] = 0; g_probs_sum[i] = 0.f; }
}

// ---------------- x fp32 -> fp16 ----------------
__global__ __launch_bounds__(256) void conv_x_kernel(const float* __restrict__ src)
{
    int i = blockIdx.x * 256 + threadIdx.x;   // TT*DD/8 items
    float4 a = ((const float4*)src)[2 * i];
    float4 b = ((const float4*)src)[2 * i + 1];
    __half2 h0 = __floats2half2_rn(a.x, a.y);
    __half2 h1 = __floats2half2_rn(a.z, a.w);
    __half2 h2 = __floats2half2_rn(b.x, b.y);
    __half2 h3 = __floats2half2_rn(b.z, b.w);
    uint4 o;
    o.x = *(uint32_t*)&h0; o.y = *(uint32_t*)&h1;
    o.z = *(uint32_t*)&h2; o.w = *(uint32_t*)&h3;
    ((uint4*)g_xh)[i] = o;
}

// ---------------- pack Wg/Wu into SMEM-image layout ----------------
__global__ __launch_bounds__(256) void pack_a_kernel(const float* __restrict__ wg,
                                                     const float* __restrict__ wu)
{
    int idx = blockIdx.x * 256 + threadIdx.x;    // NBLK*4096 items (8 halves each)
    int blk = idx >> 12;
    int rem = idx & 4095;
    int ks  = rem >> 10;
    int mat = (rem >> 9) & 1;
    int f   = (rem >> 3) & 63;
    int k8  = rem & 7;
    int e = blk >> 4, c = blk & 15;
    const float* src = (mat ? wu : wg)
        + (((size_t)e * FF + (size_t)c * FC + f) * DD + ks * 64 + k8 * 8);
    float4 a = ((const float4*)src)[0];
    float4 b = ((const float4*)src)[1];
    __half2 h0 = __floats2half2_rn(a.x, a.y);
    __half2 h1 = __floats2half2_rn(a.z, a.w);
    __half2 h2 = __floats2half2_rn(b.x, b.y);
    __half2 h3 = __floats2half2_rn(b.z, b.w);
    uint4 o;
    o.x = *(uint32_t*)&h0; o.y = *(uint32_t*)&h1;
    o.z = *(uint32_t*)&h2; o.w = *(uint32_t*)&h3;
    __half* dst = g_wpack + ((size_t)blk * CHUNK_H + ks * SLICE_H + mat * (SLICE_H / 2)
                             + f * 72 + k8 * 8);
    *(uint4*)dst = o;
}

// ---------------- pack Wd ----------------
__global__ __launch_bounds__(256) void pack_b_kernel(const float* __restrict__ wd)
{
    int idx = blockIdx.x * 256 + threadIdx.x;    // NBLK*2048 items
    int blk = idx >> 11;
    int rem = idx & 2047;
    int q   = rem >> 9;
    int d   = (rem >> 3) & 63;
    int f8  = rem & 7;
    int e = blk >> 4, c = blk & 15;
    const float* src = wd + (((size_t)e * DD + q * 64 + d) * FF + (size_t)c * FC + f8 * 8);
    float4 a = ((const float4*)src)[0];
    float4 b = ((const float4*)src)[1];
    __half2 h0 = __floats2half2_rn(a.x, a.y);
    __half2 h1 = __floats2half2_rn(a.z, a.w);
    __half2 h2 = __floats2half2_rn(b.x, b.y);
    __half2 h3 = __floats2half2_rn(b.z, b.w);
    uint4 o;
    o.x = *(uint32_t*)&h0; o.y = *(uint32_t*)&h1;
    o.z = *(uint32_t*)&h2; o.w = *(uint32_t*)&h3;
    __half* dst = g_wpack + ((size_t)blk * CHUNK_H + APART_H + q * QUART_H
                             + d * 72 + f8 * 8);
    *(uint4*)dst = o;
}

// ---------------- router (known-good) ----------------
__global__ __launch_bounds__(256) void router_kernel(const float* __restrict__ x,
                                                     const float* __restrict__ rw)
{
    __shared__ float rw_s[EE * 257];
    __shared__ float xsh[8 * 260];
    __shared__ float pacc[EE];

    const int tid  = threadIdx.x;
    const int lane = tid & 31;
    const int warp = tid >> 5;

    for (int i = tid; i < EE * DD; i += 256) {
        int e = i >> 8, d = i & 255;
        rw_s[e * 257 + d] = rw[i];
    }
    if (tid < EE) pacc[tid] = 0.f;
    __syncthreads();

    const int t = blockIdx.x * 8 + warp;
    {
        const float4* xr = (const float4*)(x + (size_t)t * DD);
        float4 a = xr[lane * 2];
        float4 b = xr[lane * 2 + 1];
        *(float4*)&xsh[warp * 260 + lane * 8]     = a;
        *(float4*)&xsh[warp * 260 + lane * 8 + 4] = b;
    }
    __syncwarp();

    float acc = 0.f;
    const float* xrow  = &xsh[warp * 260];
    const float* rwrow = &rw_s[lane * 257];
#pragma unroll 8
    for (int d = 0; d < DD; d++) acc = fmaf(xrow[d], rwrow[d], acc);
    const float logit = acc;

    float m = logit;
#pragma unroll
    for (int o = 16; o; o >>= 1) m = fmaxf(m, __shfl_xor_sync(0xffffffffu, m, o));
    float p = expf(logit - m);
    float s = p;
#pragma unroll
    for (int o = 16; o; o >>= 1) s += __shfl_xor_sync(0xffffffffu, s, o);
    atomicAdd(&pacc[lane], p / s);

    float lv = logit;
    float vals[KK]; int idxs[KK];
#pragma unroll
    for (int k = 0; k < KK; k++) {
        float v = lv; int id = lane;
#pragma unroll
        for (int o = 16; o; o >>= 1) {
            float v2 = __shfl_xor_sync(0xffffffffu, v, o);
            int   i2 = __shfl_xor_sync(0xffffffffu, id, o);
            if (v2 > v || (v2 == v && i2 < id)) { v = v2; id = i2; }
        }
        vals[k] = v; idxs[k] = id;
        if (lane == id) lv = __int_as_float(0xff800000);
    }

    float ws[KK]; float sum = 0.f;
#pragma unroll
    for (int k = 0; k < KK; k++) { ws[k] = expf(vals[k] - vals[0]); sum += ws[k]; }
    const float inv = 1.f / sum;

    if (lane == 0) {
#pragma unroll
        for (int k = 0; k < KK; k++) {
            int e   = idxs[k];
            int pos = atomicAdd(&g_counts[e], 1);
            int a   = t * KK + k;
            g_as_e[a] = e; g_as_pos[a] = pos; g_as_w[a] = ws[k] * inv;
        }
    }
    __syncthreads();
    if (tid < EE) atomicAdd(&g_probs_sum[tid], pacc[tid]);
}

// ---------------- scan offsets + aux loss + tile list ----------------
__global__ void scan_aux_kernel(float* __restrict__ out, int out_size)
{
    const int tid = threadIdx.x;   // 32 threads
    int c = g_counts[tid];
    int v = c;
#pragma unroll
    for (int o = 1; o < 32; o <<= 1) {
        int n = __shfl_up_sync(0xffffffffu, v, o);
        if (tid >= o) v += n;
    }
    g_offsets[tid] = v - c;
    if (tid == 31) g_offsets[EE] = v;

    int nt = (c + TM - 1) / TM;
    int tv = nt;
#pragma unroll
    for (int o = 1; o < 32; o <<= 1) {
        int n = __shfl_up_sync(0xffffffffu, tv, o);
        if (tid >= o) tv += n;
    }
    int tb = tv - nt;
    for (int j = 0; j < nt; j++) { g_tile_e[tb + j] = tid; g_tile_m0[tb + j] = j * TM; }
    if (tid == 31) g_ntiles = tv;

    const float invT = 1.f / (float)TT;
    float part = ((float)c * invT) * (g_probs_sum[tid] * invT);
#pragma unroll
    for (int o = 16; o; o >>= 1) part += __shfl_xor_sync(0xffffffffu, part, o);
    if (tid == 0 && out_size > TT * DD) out[(size_t)TT * DD] = (float)EE * part;
}

// ---------------- per-expert token lists + slot map ----------------
__global__ void fill_kernel()
{
    int i = blockIdx.x * blockDim.x + threadIdx.x;
    if (i < TT * KK) {
        int e    = g_as_e[i];
        int slot = g_offsets[e] + g_as_pos[i];
        g_list_tok[slot] = i >> 2;
        g_list_w[slot]   = g_as_w[i];
        g_slot[i]        = slot;
    }
}

// ---------------- fp16 mma.sync fused expert FFN, full-chunk prefetch ----------------
// SMEM layout (halves):
//   Xs  [128][264]   @ 0       (33792 h)
//   hS  [128][72]    @ 33792   (9216 h)
//   WA  [4][9216]    @ 43008   (36864 h)   all 4 A-slices of current chunk
//   WB  [4][4608]    @ 79872   (18432 h)   all 4 B-quarters of current chunk
//   mbars @ 98304h (8 x 8B), toks @ 98336h, wsh after
constexpr int XS_STRIDE = 264;
constexpr int HS_STRIDE = 72;
constexpr int OFF_H    = 33792;
constexpr int OFF_WA   = 43008;
constexpr int OFF_WB   = 79872;
constexpr int OFF_MB   = 98304;
constexpr int OFF_TOK  = 98336;
constexpr int EXP_SMEM = (OFF_TOK + 520) * 2;   // 197712 B

__global__ __launch_bounds__(256, 1)
void moe_mma_kernel()
{
    extern __shared__ __half sm[];
    __half* Xs = sm;
    __half* hS = sm + OFF_H;
    int*   toks = (int*)(sm + OFF_TOK);
    float* wsh  = (float*)(toks + 128);

    const uint32_t xs_b = smem_u32(Xs);
    const uint32_t hs_b = smem_u32(hS);
    const uint32_t wa_b = smem_u32(sm + OFF_WA);
    const uint32_t wb_b = smem_u32(sm + OFF_WB);
    const uint32_t mb   = smem_u32(sm + OFF_MB);

    const int tid  = threadIdx.x;
    const int lane = tid & 31;
    const int warp = tid >> 5;
    const int lq   = lane & 3;
    const int lh   = lane >> 2;
    const int wm   = warp & 3;        // M tile (32 rows each)
    const int wn   = warp >> 2;       // N tile (32 cols each)

    const int l7  = lane & 7;
    const int l8  = (lane >> 3) & 1;
    const int l16 = (lane >> 4) & 1;

    const int rowA0 = wm * 32 + l7 + 8 * l8;
    const int rowB0 = wn * 32 + l7 + 8 * l8;

    const uint32_t aX = xs_b + (uint32_t)((rowA0 * XS_STRIDE + l16 * 8) * 2);
    const uint32_t aH = hs_b + (uint32_t)((rowA0 * HS_STRIDE + l16 * 8) * 2);
    const uint32_t bW = (uint32_t)((rowB0 * HS_STRIDE + l16 * 8) * 2);

    if (tid == 0) {
#pragma unroll
        for (int i = 0; i < 8; i++) MBARRIER_INIT(mb + i * 8, 1);
    }
    __syncthreads();

    int ph = 0;   // single parity: every barrier flips exactly once per chunk

    const int ntiles = g_ntiles;

    for (int tile = blockIdx.x; tile < ntiles; tile += gridDim.x) {
        const int e     = g_tile_e[tile];
        const int m0    = g_tile_m0[tile];
        const int base  = g_offsets[e];
        const int count = g_offsets[e + 1] - base;

        if (tid < TM) {
            int r = m0 + tid;
            bool v = r < count;
            toks[tid] = v ? g_list_tok[base + r] : -1;
            wsh[tid]  = v ? g_list_w[base + r] : 0.f;
        }
        __syncthreads();

        const __half* wblk = g_wpack + (size_t)(e * NCH) * CHUNK_H;

        // issue chunk-0 weight copies ASAP (WA/WB free since last chunk-end sync)
        if (tid == 0) {
#pragma unroll
            for (int s = 0; s < 4; s++) {
                MBARRIER_EXPECT_TX(mb + s * 8, SLICE_H * 2);
                bulk_g2s(wa_b + (uint32_t)(s * SLICE_H * 2),
                         wblk + (size_t)s * SLICE_H, SLICE_H * 2, mb + s * 8);
            }
#pragma unroll
            for (int q = 0; q < 4; q++) {
                MBARRIER_EXPECT_TX(mb + 32 + q * 8, QUART_H * 2);
                bulk_g2s(wb_b + (uint32_t)(q * QUART_H * 2),
                         wblk + APART_H + (size_t)q * QUART_H, QUART_H * 2, mb + 32 + q * 8);
            }
        }

        // ---- stage X fp16 (cp.async; once per tile) ----
#pragma unroll 4
        for (int j = 0; j < 16; j++) {
            int idx = tid + j * 256;
            int r = idx >> 5, c8 = idx & 31;
            int t = toks[r];
            uint32_t dst = xs_b + (uint32_t)((r * XS_STRIDE + c8 * 8) * 2);
            const __half* src = g_xh + ((size_t)(t < 0 ? 0 : t) * DD + c8 * 8);
            cp16z(dst, src, t < 0 ? 0 : 16);
        }
        CP_COMMIT();

        float acc[4][2][4][4];
#pragma unroll
        for (int q = 0; q < 4; q++)
#pragma unroll
            for (int mt = 0; mt < 2; mt++)
#pragma unroll
                for (int nt = 0; nt < 4; nt++)
#pragma unroll
                    for (int r = 0; r < 4; r++) acc[q][mt][nt][r] = 0.f;

        CP_WAIT0();
        __syncthreads();   // X visible

        for (int c = 0; c < NCH; c++) {
            const __half* wch = wblk + (size_t)c * CHUNK_H;

            // ======== Phase A (fused G+U): 4 k-slices of 64 ========
            float cG[2][4][4], cU[2][4][4];
#pragma unroll
            for (int mt = 0; mt < 2; mt++)
#pragma unroll
                for (int nt = 0; nt < 4; nt++)
#pragma unroll
                    for (int r = 0; r < 4; r++) { cG[mt][nt][r] = 0.f; cU[mt][nt][r] = 0.f; }

#pragma unroll 1
            for (int ks = 0; ks < 4; ks++) {
                MBAR_WAIT(mb + ks * 8, ph);
                const uint32_t wsbB = wa_b + (uint32_t)(ks * SLICE_H * 2);
                const int d0 = ks * 64;
#pragma unroll
                for (int kk = 0; kk < 4; kk++) {
                    uint32_t a[2][4];
#pragma unroll
                    for (int mt = 0; mt < 2; mt++)
                        ldm4(a[mt], aX + (uint32_t)(((mt * 16 * XS_STRIDE) + d0 + kk * 16) * 2));
                    uint32_t bg[8], bu[8];
#pragma unroll
                    for (int nt2 = 0; nt2 < 2; nt2++) {
                        ldm4(bg + nt2 * 4, wsbB + bW + (uint32_t)(((nt2 * 16 * HS_STRIDE) + kk * 16) * 2));
                        ldm4(bu + nt2 * 4, wsbB + bW + (uint32_t)(((4608 + nt2 * 16 * HS_STRIDE) + kk * 16) * 2));
                    }
#pragma unroll
                    for (int mt = 0; mt < 2; mt++)
#pragma unroll
                        for (int nt = 0; nt < 4; nt++) {
                            int nt2 = nt >> 1, hi = nt & 1;
                            mma16(cG[mt][nt], a[mt], bg[nt2 * 4 + hi], bg[nt2 * 4 + 2 + hi]);
                            mma16(cU[mt][nt], a[mt], bu[nt2 * 4 + hi], bu[nt2 * 4 + 2 + hi]);
                        }
                }
            }

            // ---- h = silu(G) * U -> hS (fp16); sigmoid on MUFU pipe ----
#pragma unroll
            for (int mt = 0; mt < 2; mt++)
#pragma unroll
                for (int nt = 0; nt < 4; nt++) {
                    int col = wn * 32 + nt * 8 + 2 * lq;
#pragma unroll
                    for (int hf = 0; hf < 2; hf++) {
                        int row = wm * 32 + mt * 16 + hf * 8 + lh;
                        float g0 = cG[mt][nt][hf * 2 + 0];
                        float g1 = cG[mt][nt][hf * 2 + 1];
                        float s0 = __fdividef(g0, 1.f + __expf(-g0));
                        float s1 = __fdividef(g1, 1.f + __expf(-g1));
                        float h0 = s0 * cU[mt][nt][hf * 2 + 0];
                        float h1 = s1 * cU[mt][nt][hf * 2 + 1];
                        __half2 o2 = __floats2half2_rn(h0, h1);
                        *(__half2*)&hS[row * HS_STRIDE + col] = o2;
                    }
                }
            __syncthreads();   // hS visible to all warps

            // ======== Phase B: out += h @ Wd^T (4 quarters of D) ========
#pragma unroll 1
            for (int q = 0; q < 4; q++) {
                MBAR_WAIT(mb + 32 + q * 8, ph);
                const uint32_t wdbB = wb_b + (uint32_t)(q * QUART_H * 2);
#pragma unroll
                for (int kk = 0; kk < 4; kk++) {
                    uint32_t a[2][4];
#pragma unroll
                    for (int mt = 0; mt < 2; mt++)
                        ldm4(a[mt], aH + (uint32_t)(((mt * 16 * HS_STRIDE) + kk * 16) * 2));
                    uint32_t bbr[8];
#pragma unroll
                    for (int nt2 = 0; nt2 < 2; nt2++)
                        ldm4(bbr + nt2 * 4, wdbB + bW + (uint32_t)(((nt2 * 16 * HS_STRIDE) + kk * 16) * 2));
#pragma unroll
                    for (int mt = 0; mt < 2; mt++)
#pragma unroll
                        for (int nt = 0; nt < 4; nt++) {
                            int nt2 = nt >> 1, hi = nt & 1;
                            mma16(acc[q][mt][nt], a[mt], bbr[nt2 * 4 + hi], bbr[nt2 * 4 + 2 + hi]);
                        }
                }
            }

            __syncthreads();   // chunk end: WA/WB/hS reads complete
            ph ^= 1;

            // issue next chunk's copies immediately (overlaps nothing behind it)
            if (c < NCH - 1 && tid == 0) {
                const __half* wnx = wblk + (size_t)(c + 1) * CHUNK_H;
#pragma unroll
                for (int s = 0; s < 4; s++) {
                    MBARRIER_EXPECT_TX(mb + s * 8, SLICE_H * 2);
                    bulk_g2s(wa_b + (uint32_t)(s * SLICE_H * 2),
                             wnx + (size_t)s * SLICE_H, SLICE_H * 2, mb + s * 8);
                }
#pragma unroll
                for (int q = 0; q < 4; q++) {
                    MBARRIER_EXPECT_TX(mb + 32 + q * 8, QUART_H * 2);
                    bulk_g2s(wb_b + (uint32_t)(q * QUART_H * 2),
                             wnx + APART_H + (size_t)q * QUART_H, QUART_H * 2, mb + 32 + q * 8);
                }
            }
        }

        // ---- epilogue: weighted write to scratch ----
#pragma unroll
        for (int q = 0; q < 4; q++)
#pragma unroll
            for (int mt = 0; mt < 2; mt++)
#pragma unroll
                for (int hf = 0; hf < 2; hf++) {
                    int tr = wm * 32 + mt * 16 + hf * 8 + lh;
                    if (m0 + tr < count) {
                        float w = wsh[tr];
                        float* dst = g_scratch + (size_t)(base + m0 + tr) * DD
                                   + q * 64 + wn * 32 + 2 * lq;
#pragma unroll
                        for (int nt = 0; nt < 4; nt++) {
                            float2 v;
                            v.x = acc[q][mt][nt][hf * 2 + 0] * w;
                            v.y = acc[q][mt][nt][hf * 2 + 1] * w;
                            *(float2*)(dst + nt * 8) = v;
                        }
                    }
                }
        __syncthreads();   // protect toks/wsh/Xs before next tile
    }
}

// ---------------- combine: out[t] = sum of token's 4 weighted slots ----------------
__global__ __launch_bounds__(256) void combine_kernel(float* __restrict__ out)
{
    int idx = blockIdx.x * 256 + threadIdx.x;     // TT*64 float4 items
    int t = idx >> 6, q = (idx & 63) * 4;
    const int* sl = g_slot + t * 4;
    float4 a = *(const float4*)(g_scratch + (size_t)sl[0] * DD + q);
    float4 b = *(const float4*)(g_scratch + (size_t)sl[1] * DD + q);
    float4 c = *(const float4*)(g_scratch + (size_t)sl[2] * DD + q);
    float4 d = *(const float4*)(g_scratch + (size_t)sl[3] * DD + q);
    float4 r;
    r.x = a.x + b.x + c.x + d.x;
    r.y = a.y + b.y + c.y + d.y;
    r.z = a.z + b.z + c.z + d.z;
    r.w = a.w + b.w + c.w + d.w;
    *(float4*)(out + (size_t)t * DD + q) = r;
}

// ---------------- launch ----------------
extern "C" void kernel_launch(void* const* d_in, const int* in_sizes, int n_in,
                              void* d_out, int out_size)
{
    const float* x  = (const float*)d_in[0];
    const float* rw = (const float*)d_in[1];
    const float* wg = (const float*)d_in[2];
    const float* wu = (const float*)d_in[3];
    const float* wd = (const float*)d_in[4];
    float* out = (float*)d_out;

    cudaMemsetAsync(d_out, 0, (size_t)out_size * sizeof(float));
    init_kernel<<<1, 32>>>();
    router_kernel<<<TT / 8, 256>>>(x, rw);
    scan_aux_kernel<<<1, 32>>>(out, out_size);
    fill_kernel<<<(TT * KK + 255) / 256, 256>>>();

    conv_x_kernel<<<TT * DD / 8 / 256, 256>>>(x);
    pack_a_kernel<<<NBLK * 4096 / 256, 256>>>(wg, wu);
    pack_b_kernel<<<NBLK * 2048 / 256, 256>>>(wd);

    cudaFuncSetAttribute(moe_mma_kernel,
                         cudaFuncAttributeMaxDynamicSharedMemorySize, EXP_SMEM);
    moe_mma_kernel<<<148, 256, EXP_SMEM>>>();
    combine_kernel<<<TT * 64 / 256, 256>>>(out);
}

// round 14
// speedup vs baseline: 1.2020x; 1.0391x over previous
#include <cuda_runtime.h>
#include <cuda_fp16.h>
#include <math.h>
#include <stdint.h>

#define TT 8192
#define DD 256
#define FF 1024
#define EE 32
#define KK 4
#define TM 128            // tokens per tile (MMA M)
#define FC 64             // ffn chunk
#define NCH (FF / FC)     // 16

// packed-weight block geometry (halves)
#define SLICE_H  9216     // [2 mat][64 f][72]
#define QUART_H  4608     // [64 d][72]
#define APART_H  (4 * SLICE_H)            // 36864
#define CHUNK_H  (APART_H + 4 * QUART_H)  // 55296
#define NBLK     (EE * NCH)               // 512

// ---------------- scratch globals ----------------
__device__ int   g_counts[EE];
__device__ int   g_offsets[EE + 1];
__device__ float g_probs_sum[EE];
__device__ int   g_as_e[TT * KK];
__device__ int   g_as_pos[TT * KK];
__device__ float g_as_w[TT * KK];
__device__ int   g_list_tok[TT * KK];
__device__ float g_list_w[TT * KK];
__device__ int   g_slot[TT * KK];
__device__ int   g_tile_e[2048];
__device__ int   g_tile_m0[2048];
__device__ int   g_ntiles;
__device__ float g_scratch[(size_t)TT * KK * DD];       // 32 MB partials
__device__ __half g_xh[(size_t)TT * DD];                // 4 MB fp16 x
__device__ __half g_wpack[(size_t)NBLK * CHUNK_H];      // 56.6 MB packed weights

// ---------------- PTX helpers ----------------
__device__ __forceinline__ void mma16(float* c, const uint32_t* a, uint32_t b0, uint32_t b1) {
    asm("mma.sync.aligned.m16n8k16.row.col.f32.f16.f16.f32 "
        "{%0,%1,%2,%3},{%4,%5,%6,%7},{%8,%9},{%0,%1,%2,%3};"
        : "+f"(c[0]), "+f"(c[1]), "+f"(c[2]), "+f"(c[3])
        : "r"(a[0]), "r"(a[1]), "r"(a[2]), "r"(a[3]), "r"(b0), "r"(b1));
}
__device__ __forceinline__ void ldm4(uint32_t* r, uint32_t addr) {
    asm volatile("ldmatrix.sync.aligned.m8n8.x4.shared.b16 {%0,%1,%2,%3}, [%4];"
        : "=r"(r[0]), "=r"(r[1]), "=r"(r[2]), "=r"(r[3]) : "r"(addr));
}
__device__ __forceinline__ void cp16z(uint32_t dst, const void* src, int ssz) {
    asm volatile("cp.async.cg.shared.global [%0], [%1], 16, %2;" :: "r"(dst), "l"(src), "r"(ssz));
}
#define CP_COMMIT() asm volatile("cp.async.commit_group;" ::: "memory")
#define CP_WAIT0()  asm volatile("cp.async.wait_group 0;" ::: "memory")

__device__ __forceinline__ void bulk_g2s(uint32_t dst, const void* src, uint32_t bytes,
                                         uint32_t mbar) {
    asm volatile("cp.async.bulk.shared::cta.global.mbarrier::complete_tx::bytes "
                 "[%0], [%1], %2, [%3];"
                 :: "r"(dst), "l"(src), "r"(bytes), "r"(mbar) : "memory");
}
#define MBARRIER_INIT(a, n) \
    asm volatile("mbarrier.init.shared.b64 [%0], %1;" :: "r"((uint32_t)(a)), "r"((uint32_t)(n)) : "memory")
#define MBARRIER_EXPECT_TX(a, b) \
    asm volatile("mbarrier.arrive.expect_tx.shared.b64 _, [%0], %1;" :: "r"((uint32_t)(a)), "r"((uint32_t)(b)) : "memory")
#define MBAR_WAIT(a, ph) do {                                                        \
    uint32_t _m = (uint32_t)(a); uint32_t _p = (uint32_t)(ph); uint32_t _d;          \
    asm volatile("{\n\t.reg .pred p;\n\t"                                            \
        "mbarrier.try_wait.parity.acquire.cta.shared::cta.b64 p, [%1], %2;\n\t"      \
        "selp.b32 %0, 1, 0, p;\n\t}"                                                 \
        : "=r"(_d) : "r"(_m), "r"(_p) : "memory");                                   \
    if (!_d) {                                                                        \
        asm volatile("{\n\t.reg .pred P1;\n\t"                                       \
            "WL_%=:\n\t"                                                             \
            "mbarrier.try_wait.parity.acquire.cta.shared::cta.b64 P1, [%0], %1, 0x989680;\n\t" \
            "@P1 bra.uni WD_%=;\n\t"                                                 \
            "bra.uni WL_%=;\n\t"                                                     \
            "WD_%=:\n\t}"                                                            \
            :: "r"(_m), "r"(_p) : "memory");                                         \
    } } while (0)

__device__ __forceinline__ uint32_t smem_u32(const void* p) {
    uint32_t a;
    asm("{ .reg .u64 t; cvta.to.shared.u64 t, %1; cvt.u32.u64 %0, t; }" : "=r"(a) : "l"(p));
    return a;
}

// ---------------- init ----------------
__global__ void init_kernel()
{
    int i = threadIdx.x;
    if (i < EE) { g_counts[i] = 0; g_probs_sum[i] = 0.f; }
}

// ---------------- x fp32 -> fp16 ----------------
__global__ __launch_bounds__(256) void conv_x_kernel(const float* __restrict__ src)
{
    int i = blockIdx.x * 256 + threadIdx.x;   // TT*DD/8 items
    float4 a = ((const float4*)src)[2 * i];
    float4 b = ((const float4*)src)[2 * i + 1];
    __half2 h0 = __floats2half2_rn(a.x, a.y);
    __half2 h1 = __floats2half2_rn(a.z, a.w);
    __half2 h2 = __floats2half2_rn(b.x, b.y);
    __half2 h3 = __floats2half2_rn(b.z, b.w);
    uint4 o;
    o.x = *(uint32_t*)&h0; o.y = *(uint32_t*)&h1;
    o.z = *(uint32_t*)&h2; o.w = *(uint32_t*)&h3;
    ((uint4*)g_xh)[i] = o;
}

// ---------------- pack Wg/Wu into SMEM-image layout ----------------
__global__ __launch_bounds__(256) void pack_a_kernel(const float* __restrict__ wg,
                                                     const float* __restrict__ wu)
{
    int idx = blockIdx.x * 256 + threadIdx.x;    // NBLK*4096 items (8 halves each)
    int blk = idx >> 12;
    int rem = idx & 4095;
    int ks  = rem >> 10;
    int mat = (rem >> 9) & 1;
    int f   = (rem >> 3) & 63;
    int k8  = rem & 7;
    int e = blk >> 4, c = blk & 15;
    const float* src = (mat ? wu : wg)
        + (((size_t)e * FF + (size_t)c * FC + f) * DD + ks * 64 + k8 * 8);
    float4 a = ((const float4*)src)[0];
    float4 b = ((const float4*)src)[1];
    __half2 h0 = __floats2half2_rn(a.x, a.y);
    __half2 h1 = __floats2half2_rn(a.z, a.w);
    __half2 h2 = __floats2half2_rn(b.x, b.y);
    __half2 h3 = __floats2half2_rn(b.z, b.w);
    uint4 o;
    o.x = *(uint32_t*)&h0; o.y = *(uint32_t*)&h1;
    o.z = *(uint32_t*)&h2; o.w = *(uint32_t*)&h3;
    __half* dst = g_wpack + ((size_t)blk * CHUNK_H + ks * SLICE_H + mat * (SLICE_H / 2)
                             + f * 72 + k8 * 8);
    *(uint4*)dst = o;
}

// ---------------- pack Wd ----------------
__global__ __launch_bounds__(256) void pack_b_kernel(const float* __restrict__ wd)
{
    int idx = blockIdx.x * 256 + threadIdx.x;    // NBLK*2048 items
    int blk = idx >> 11;
    int rem = idx & 2047;
    int q   = rem >> 9;
    int d   = (rem >> 3) & 63;
    int f8  = rem & 7;
    int e = blk >> 4, c = blk & 15;
    const float* src = wd + (((size_t)e * DD + q * 64 + d) * FF + (size_t)c * FC + f8 * 8);
    float4 a = ((const float4*)src)[0];
    float4 b = ((const float4*)src)[1];
    __half2 h0 = __floats2half2_rn(a.x, a.y);
    __half2 h1 = __floats2half2_rn(a.z, a.w);
    __half2 h2 = __floats2half2_rn(b.x, b.y);
    __half2 h3 = __floats2half2_rn(b.z, b.w);
    uint4 o;
    o.x = *(uint32_t*)&h0; o.y = *(uint32_t*)&h1;
    o.z = *(uint32_t*)&h2; o.w = *(uint32_t*)&h3;
    __half* dst = g_wpack + ((size_t)blk * CHUNK_H + APART_H + q * QUART_H
                             + d * 72 + f8 * 8);
    *(uint4*)dst = o;
}

// ---------------- router (known-good) ----------------
__global__ __launch_bounds__(256) void router_kernel(const float* __restrict__ x,
                                                     const float* __restrict__ rw)
{
    __shared__ float rw_s[EE * 257];
    __shared__ float xsh[8 * 260];
    __shared__ float pacc[EE];

    const int tid  = threadIdx.x;
    const int lane = tid & 31;
    const int warp = tid >> 5;

    for (int i = tid; i < EE * DD; i += 256) {
        int e = i >> 8, d = i & 255;
        rw_s[e * 257 + d] = rw[i];
    }
    if (tid < EE) pacc[tid] = 0.f;
    __syncthreads();

    const int t = blockIdx.x * 8 + warp;
    {
        const float4* xr = (const float4*)(x + (size_t)t * DD);
        float4 a = xr[lane * 2];
        float4 b = xr[lane * 2 + 1];
        *(float4*)&xsh[warp * 260 + lane * 8]     = a;
        *(float4*)&xsh[warp * 260 + lane * 8 + 4] = b;
    }
    __syncwarp();

    float acc = 0.f;
    const float* xrow  = &xsh[warp * 260];
    const float* rwrow = &rw_s[lane * 257];
#pragma unroll 8
    for (int d = 0; d < DD; d++) acc = fmaf(xrow[d], rwrow[d], acc);
    const float logit = acc;

    float m = logit;
#pragma unroll
    for (int o = 16; o; o >>= 1) m = fmaxf(m, __shfl_xor_sync(0xffffffffu, m, o));
    float p = expf(logit - m);
    float s = p;
#pragma unroll
    for (int o = 16; o; o >>= 1) s += __shfl_xor_sync(0xffffffffu, s, o);
    atomicAdd(&pacc[lane], p / s);

    float lv = logit;
    float vals[KK]; int idxs[KK];
#pragma unroll
    for (int k = 0; k < KK; k++) {
        float v = lv; int id = lane;
#pragma unroll
        for (int o = 16; o; o >>= 1) {
            float v2 = __shfl_xor_sync(0xffffffffu, v, o);
            int   i2 = __shfl_xor_sync(0xffffffffu, id, o);
            if (v2 > v || (v2 == v && i2 < id)) { v = v2; id = i2; }
        }
        vals[k] = v; idxs[k] = id;
        if (lane == id) lv = __int_as_float(0xff800000);
    }

    float ws[KK]; float sum = 0.f;
#pragma unroll
    for (int k = 0; k < KK; k++) { ws[k] = expf(vals[k] - vals[0]); sum += ws[k]; }
    const float inv = 1.f / sum;

    if (lane == 0) {
#pragma unroll
        for (int k = 0; k < KK; k++) {
            int e   = idxs[k];
            int pos = atomicAdd(&g_counts[e], 1);
            int a   = t * KK + k;
            g_as_e[a] = e; g_as_pos[a] = pos; g_as_w[a] = ws[k] * inv;
        }
    }
    __syncthreads();
    if (tid < EE) atomicAdd(&g_probs_sum[tid], pacc[tid]);
}

// ---------------- scan offsets + aux loss + tile list ----------------
__global__ void scan_aux_kernel(float* __restrict__ out, int out_size)
{
    const int tid = threadIdx.x;   // 32 threads
    int c = g_counts[tid];
    int v = c;
#pragma unroll
    for (int o = 1; o < 32; o <<= 1) {
        int n = __shfl_up_sync(0xffffffffu, v, o);
        if (tid >= o) v += n;
    }
    g_offsets[tid] = v - c;
    if (tid == 31) g_offsets[EE] = v;

    int nt = (c + TM - 1) / TM;
    int tv = nt;
#pragma unroll
    for (int o = 1; o < 32; o <<= 1) {
        int n = __shfl_up_sync(0xffffffffu, tv, o);
        if (tid >= o) tv += n;
    }
    int tb = tv - nt;
    for (int j = 0; j < nt; j++) { g_tile_e[tb + j] = tid; g_tile_m0[tb + j] = j * TM; }
    if (tid == 31) g_ntiles = tv;

    const float invT = 1.f / (float)TT;
    float part = ((float)c * invT) * (g_probs_sum[tid] * invT);
#pragma unroll
    for (int o = 16; o; o >>= 1) part += __shfl_xor_sync(0xffffffffu, part, o);
    if (tid == 0 && out_size > TT * DD) out[(size_t)TT * DD] = (float)EE * part;
}

// ---------------- per-expert token lists + slot map ----------------
__global__ void fill_kernel()
{
    int i = blockIdx.x * blockDim.x + threadIdx.x;
    if (i < TT * KK) {
        int e    = g_as_e[i];
        int slot = g_offsets[e] + g_as_pos[i];
        g_list_tok[slot] = i >> 2;
        g_list_w[slot]   = g_as_w[i];
        g_slot[i]        = slot;
    }
}

// ---------------- fp16 mma.sync fused expert FFN, rotated prefetch ----------------
// SMEM layout (halves):
//   Xs  [128][264]   @ 0       (33792 h)
//   hS  [128][72]    @ 33792   (9216 h)
//   WA  [4][9216]    @ 43008   (36864 h)   all 4 A-slices of current chunk
//   WB  [4][4608]    @ 79872   (18432 h)   all 4 B-quarters of current chunk
//   mbars @ 98304h (8 x 8B), toks @ 98336h, wsh after
constexpr int XS_STRIDE = 264;
constexpr int HS_STRIDE = 72;
constexpr int OFF_H    = 33792;
constexpr int OFF_WA   = 43008;
constexpr int OFF_WB   = 79872;
constexpr int OFF_MB   = 98304;
constexpr int OFF_TOK  = 98336;
constexpr int EXP_SMEM = (OFF_TOK + 520) * 2;   // 197712 B

__global__ __launch_bounds__(256, 1)
void moe_mma_kernel()
{
    extern __shared__ __half sm[];
    __half* Xs = sm;
    __half* hS = sm + OFF_H;
    int*   toks = (int*)(sm + OFF_TOK);
    float* wsh  = (float*)(toks + 128);

    const uint32_t xs_b = smem_u32(Xs);
    const uint32_t hs_b = smem_u32(hS);
    const uint32_t wa_b = smem_u32(sm + OFF_WA);
    const uint32_t wb_b = smem_u32(sm + OFF_WB);
    const uint32_t mb   = smem_u32(sm + OFF_MB);

    const int tid  = threadIdx.x;
    const int lane = tid & 31;
    const int warp = tid >> 5;
    const int lq   = lane & 3;
    const int lh   = lane >> 2;
    const int wm   = warp & 3;        // M tile (32 rows each)
    const int wn   = warp >> 2;       // N tile (32 cols each)

    const int l7  = lane & 7;
    const int l8  = (lane >> 3) & 1;
    const int l16 = (lane >> 4) & 1;

    const int rowA0 = wm * 32 + l7 + 8 * l8;
    const int rowB0 = wn * 32 + l7 + 8 * l8;

    const uint32_t aX = xs_b + (uint32_t)((rowA0 * XS_STRIDE + l16 * 8) * 2);
    const uint32_t aH = hs_b + (uint32_t)((rowA0 * HS_STRIDE + l16 * 8) * 2);
    const uint32_t bW = (uint32_t)((rowB0 * HS_STRIDE + l16 * 8) * 2);

    if (tid == 0) {
#pragma unroll
        for (int i = 0; i < 8; i++) MBARRIER_INIT(mb + i * 8, 1);
    }
    __syncthreads();

    int ph = 0;   // running parity: every barrier completes once per chunk
    bool first = true;

    const int ntiles = g_ntiles;

    for (int tile = blockIdx.x; tile < ntiles; tile += gridDim.x) {
        const int e     = g_tile_e[tile];
        const int m0    = g_tile_m0[tile];
        const int base  = g_offsets[e];
        const int count = g_offsets[e + 1] - base;

        if (tid < TM) {
            int r = m0 + tid;
            bool v = r < count;
            toks[tid] = v ? g_list_tok[base + r] : -1;
            wsh[tid]  = v ? g_list_w[base + r] : 0.f;
        }
        __syncthreads();

        const __half* wblk = g_wpack + (size_t)(e * NCH) * CHUNK_H;

        // very first tile of this CTA: prime chunk-0 copies
        if (first && tid == 0) {
#pragma unroll
            for (int s = 0; s < 4; s++) {
                MBARRIER_EXPECT_TX(mb + s * 8, SLICE_H * 2);
                bulk_g2s(wa_b + (uint32_t)(s * SLICE_H * 2),
                         wblk + (size_t)s * SLICE_H, SLICE_H * 2, mb + s * 8);
            }
#pragma unroll
            for (int q = 0; q < 4; q++) {
                MBARRIER_EXPECT_TX(mb + 32 + q * 8, QUART_H * 2);
                bulk_g2s(wb_b + (uint32_t)(q * QUART_H * 2),
                         wblk + APART_H + (size_t)q * QUART_H, QUART_H * 2, mb + 32 + q * 8);
            }
        }
        first = false;

        // ---- stage X fp16 (cp.async; once per tile) ----
#pragma unroll 4
        for (int j = 0; j < 16; j++) {
            int idx = tid + j * 256;
            int r = idx >> 5, c8 = idx & 31;
            int t = toks[r];
            uint32_t dst = xs_b + (uint32_t)((r * XS_STRIDE + c8 * 8) * 2);
            const __half* src = g_xh + ((size_t)(t < 0 ? 0 : t) * DD + c8 * 8);
            cp16z(dst, src, t < 0 ? 0 : 16);
        }
        CP_COMMIT();

        float acc[4][2][4][4];
#pragma unroll
        for (int q = 0; q < 4; q++)
#pragma unroll
            for (int mt = 0; mt < 2; mt++)
#pragma unroll
                for (int nt = 0; nt < 4; nt++)
#pragma unroll
                    for (int r = 0; r < 4; r++) acc[q][mt][nt][r] = 0.f;

        CP_WAIT0();
        __syncthreads();   // X visible

        for (int c = 0; c < NCH; c++) {
            // next weight block to prefetch (next chunk, or next tile's chunk 0)
            const __half* wnx;
            if (c < NCH - 1) {
                wnx = wblk + (size_t)(c + 1) * CHUNK_H;
            } else {
                int t2 = tile + gridDim.x;
                wnx = (t2 < ntiles)
                    ? g_wpack + (size_t)(g_tile_e[t2] * NCH) * CHUNK_H : (const __half*)0;
            }

            // ======== Phase A (fused G+U): 4 k-slices of 64 ========
            float cG[2][4][4], cU[2][4][4];
#pragma unroll
            for (int mt = 0; mt < 2; mt++)
#pragma unroll
                for (int nt = 0; nt < 4; nt++)
#pragma unroll
                    for (int r = 0; r < 4; r++) { cG[mt][nt][r] = 0.f; cU[mt][nt][r] = 0.f; }

#pragma unroll 1
            for (int ks = 0; ks < 4; ks++) {
                MBAR_WAIT(mb + ks * 8, ph);
                const uint32_t wsbB = wa_b + (uint32_t)(ks * SLICE_H * 2);
                const int d0 = ks * 64;
#pragma unroll
                for (int kk = 0; kk < 4; kk++) {
                    uint32_t a[2][4];
#pragma unroll
                    for (int mt = 0; mt < 2; mt++)
                        ldm4(a[mt], aX + (uint32_t)(((mt * 16 * XS_STRIDE) + d0 + kk * 16) * 2));
                    uint32_t bg[8], bu[8];
#pragma unroll
                    for (int nt2 = 0; nt2 < 2; nt2++) {
                        ldm4(bg + nt2 * 4, wsbB + bW + (uint32_t)(((nt2 * 16 * HS_STRIDE) + kk * 16) * 2));
                        ldm4(bu + nt2 * 4, wsbB + bW + (uint32_t)(((4608 + nt2 * 16 * HS_STRIDE) + kk * 16) * 2));
                    }
#pragma unroll
                    for (int mt = 0; mt < 2; mt++)
#pragma unroll
                        for (int nt = 0; nt < 4; nt++) {
                            int nt2 = nt >> 1, hi = nt & 1;
                            mma16(cG[mt][nt], a[mt], bg[nt2 * 4 + hi], bg[nt2 * 4 + 2 + hi]);
                            mma16(cU[mt][nt], a[mt], bu[nt2 * 4 + hi], bu[nt2 * 4 + 2 + hi]);
                        }
                }
            }

            // ---- h = silu(G) * U -> hS (fp16); sigmoid on MUFU pipe ----
#pragma unroll
            for (int mt = 0; mt < 2; mt++)
#pragma unroll
                for (int nt = 0; nt < 4; nt++) {
                    int col = wn * 32 + nt * 8 + 2 * lq;
#pragma unroll
                    for (int hf = 0; hf < 2; hf++) {
                        int row = wm * 32 + mt * 16 + hf * 8 + lh;
                        float g0 = cG[mt][nt][hf * 2 + 0];
                        float g1 = cG[mt][nt][hf * 2 + 1];
                        float s0 = __fdividef(g0, 1.f + __expf(-g0));
                        float s1 = __fdividef(g1, 1.f + __expf(-g1));
                        float h0 = s0 * cU[mt][nt][hf * 2 + 0];
                        float h1 = s1 * cU[mt][nt][hf * 2 + 1];
                        __half2 o2 = __floats2half2_rn(h0, h1);
                        *(__half2*)&hS[row * HS_STRIDE + col] = o2;
                    }
                }
            __syncthreads();   // hS visible + all warps done reading WA

            // prefetch next WA slices NOW — overlaps all of Phase B
            if (wnx && tid == 0) {
#pragma unroll
                for (int s = 0; s < 4; s++) {
                    MBARRIER_EXPECT_TX(mb + s * 8, SLICE_H * 2);
                    bulk_g2s(wa_b + (uint32_t)(s * SLICE_H * 2),
                             wnx + (size_t)s * SLICE_H, SLICE_H * 2, mb + s * 8);
                }
            }

            // ======== Phase B: out += h @ Wd^T (4 quarters of D) ========
#pragma unroll 1
            for (int q = 0; q < 4; q++) {
                MBAR_WAIT(mb + 32 + q * 8, ph);
                const uint32_t wdbB = wb_b + (uint32_t)(q * QUART_H * 2);
#pragma unroll
                for (int kk = 0; kk < 4; kk++) {
                    uint32_t a[2][4];
#pragma unroll
                    for (int mt = 0; mt < 2; mt++)
                        ldm4(a[mt], aH + (uint32_t)(((mt * 16 * HS_STRIDE) + kk * 16) * 2));
                    uint32_t bbr[8];
#pragma unroll
                    for (int nt2 = 0; nt2 < 2; nt2++)
                        ldm4(bbr + nt2 * 4, wdbB + bW + (uint32_t)(((nt2 * 16 * HS_STRIDE) + kk * 16) * 2));
#pragma unroll
                    for (int mt = 0; mt < 2; mt++)
#pragma unroll
                        for (int nt = 0; nt < 4; nt++) {
                            int nt2 = nt >> 1, hi = nt & 1;
                            mma16(acc[q][mt][nt], a[mt], bbr[nt2 * 4 + hi], bbr[nt2 * 4 + 2 + hi]);
                        }
                }
            }

            __syncthreads();   // chunk end: WB/hS reads complete
            ph ^= 1;

            // prefetch next WB quarters — overlaps next Phase A (or epilogue)
            if (wnx && tid == 0) {
#pragma unroll
                for (int q = 0; q < 4; q++) {
                    MBARRIER_EXPECT_TX(mb + 32 + q * 8, QUART_H * 2);
                    bulk_g2s(wb_b + (uint32_t)(q * QUART_H * 2),
                             wnx + APART_H + (size_t)q * QUART_H, QUART_H * 2, mb + 32 + q * 8);
                }
            }
        }

        // ---- epilogue: weighted write to scratch ----
#pragma unroll
        for (int q = 0; q < 4; q++)
#pragma unroll
            for (int mt = 0; mt < 2; mt++)
#pragma unroll
                for (int hf = 0; hf < 2; hf++) {
                    int tr = wm * 32 + mt * 16 + hf * 8 + lh;
                    if (m0 + tr < count) {
                        float w = wsh[tr];
                        float* dst = g_scratch + (size_t)(base + m0 + tr) * DD
                                   + q * 64 + wn * 32 + 2 * lq;
#pragma unroll
                        for (int nt = 0; nt < 4; nt++) {
                            float2 v;
                            v.x = acc[q][mt][nt][hf * 2 + 0] * w;
                            v.y = acc[q][mt][nt][hf * 2 + 1] * w;
                            *(float2*)(dst + nt * 8) = v;
                        }
                    }
                }
        __syncthreads();   // protect toks/wsh/Xs before next tile
    }
}

// ---------------- combine: out[t] = sum of token's 4 weighted slots ----------------
__global__ __launch_bounds__(256) void combine_kernel(float* __restrict__ out)
{
    int idx = blockIdx.x * 256 + threadIdx.x;     // TT*64 float4 items
    int t = idx >> 6, q = (idx & 63) * 4;
    const int* sl = g_slot + t * 4;
    float4 a = *(const float4*)(g_scratch + (size_t)sl[0] * DD + q);
    float4 b = *(const float4*)(g_scratch + (size_t)sl[1] * DD + q);
    float4 c = *(const float4*)(g_scratch + (size_t)sl[2] * DD + q);
    float4 d = *(const float4*)(g_scratch + (size_t)sl[3] * DD + q);
    float4 r;
    r.x = a.x + b.x + c.x + d.x;
    r.y = a.y + b.y + c.y + d.y;
    r.z = a.z + b.z + c.z + d.z;
    r.w = a.w + b.w + c.w + d.w;
    *(float4*)(out + (size_t)t * DD + q) = r;
}

// ---------------- launch ----------------
extern "C" void kernel_launch(void* const* d_in, const int* in_sizes, int n_in,
                              void* d_out, int out_size)
{
    const float* x  = (const float*)d_in[0];
    const float* rw = (const float*)d_in[1];
    const float* wg = (const float*)d_in[2];
    const float* wu = (const float*)d_in[3];
    const float* wd = (const float*)d_in[4];
    float* out = (float*)d_out;

    cudaMemsetAsync(d_out, 0, (size_t)out_size * sizeof(float));
    init_kernel<<<1, 32>>>();
    router_kernel<<<TT / 8, 256>>>(x, rw);
    scan_aux_kernel<<<1, 32>>>(out, out_size);
    fill_kernel<<<(TT * KK + 255) / 256, 256>>>();

    conv_x_kernel<<<TT * DD / 8 / 256, 256>>>(x);
    pack_a_kernel<<<NBLK * 4096 / 256, 256>>>(wg, wu);
    pack_b_kernel<<<NBLK * 2048 / 256, 256>>>(wd);

    cudaFuncSetAttribute(moe_mma_kernel,
                         cudaFuncAttributeMaxDynamicSharedMemorySize, EXP_SMEM);
    moe_mma_kernel<<<148, 256, EXP_SMEM>>>();
    combine_kernel<<<TT * 64 / 256, 256>>>(out);
}

// round 15
// speedup vs baseline: 1.2189x; 1.0140x over previous
#include <cuda_runtime.h>
#include <cuda_fp16.h>
#include <math.h>
#include <stdint.h>

#define TT 8192
#define DD 256
#define FF 1024
#define EE 32
#define KK 4
#define TM 128            // tokens per tile (MMA M)
#define FC 64             // ffn chunk
#define NCH (FF / FC)     // 16

// packed-weight block geometry (halves)
#define SLICE_H  9216     // [2 mat][64 f][72]
#define QUART_H  4608     // [64 d][72]
#define APART_H  (4 * SLICE_H)            // 36864
#define CHUNK_H  (APART_H + 4 * QUART_H)  // 55296
#define NBLK     (EE * NCH)               // 512

// ---------------- scratch globals ----------------
__device__ int   g_counts[EE];
__device__ int   g_offsets[EE + 1];
__device__ float g_probs_sum[EE];
__device__ int   g_as_e[TT * KK];
__device__ int   g_as_pos[TT * KK];
__device__ float g_as_w[TT * KK];
__device__ int   g_list_tok[TT * KK];
__device__ float g_list_w[TT * KK];
__device__ int   g_slot[TT * KK];
__device__ int   g_tile_e[2048];
__device__ int   g_tile_m0[2048];
__device__ int   g_ntiles;
__device__ float g_scratch[(size_t)TT * KK * DD];       // 32 MB partials
__device__ __half g_xh[(size_t)TT * DD];                // 4 MB fp16 x
__device__ __half g_wpack[(size_t)NBLK * CHUNK_H];      // 56.6 MB packed weights

// ---------------- PTX helpers ----------------
__device__ __forceinline__ void mma16(float* c, const uint32_t* a, uint32_t b0, uint32_t b1) {
    asm("mma.sync.aligned.m16n8k16.row.col.f32.f16.f16.f32 "
        "{%0,%1,%2,%3},{%4,%5,%6,%7},{%8,%9},{%0,%1,%2,%3};"
        : "+f"(c[0]), "+f"(c[1]), "+f"(c[2]), "+f"(c[3])
        : "r"(a[0]), "r"(a[1]), "r"(a[2]), "r"(a[3]), "r"(b0), "r"(b1));
}
__device__ __forceinline__ void ldm4(uint32_t* r, uint32_t addr) {
    asm volatile("ldmatrix.sync.aligned.m8n8.x4.shared.b16 {%0,%1,%2,%3}, [%4];"
        : "=r"(r[0]), "=r"(r[1]), "=r"(r[2]), "=r"(r[3]) : "r"(addr));
}
__device__ __forceinline__ void cp16z(uint32_t dst, const void* src, int ssz) {
    asm volatile("cp.async.cg.shared.global [%0], [%1], 16, %2;" :: "r"(dst), "l"(src), "r"(ssz));
}
#define CP_COMMIT() asm volatile("cp.async.commit_group;" ::: "memory")
#define CP_WAIT0()  asm volatile("cp.async.wait_group 0;" ::: "memory")

__device__ __forceinline__ void bulk_g2s(uint32_t dst, const void* src, uint32_t bytes,
                                         uint32_t mbar) {
    asm volatile("cp.async.bulk.shared::cta.global.mbarrier::complete_tx::bytes "
                 "[%0], [%1], %2, [%3];"
                 :: "r"(dst), "l"(src), "r"(bytes), "r"(mbar) : "memory");
}
#define MBARRIER_INIT(a, n) \
    asm volatile("mbarrier.init.shared.b64 [%0], %1;" :: "r"((uint32_t)(a)), "r"((uint32_t)(n)) : "memory")
#define MBARRIER_EXPECT_TX(a, b) \
    asm volatile("mbarrier.arrive.expect_tx.shared.b64 _, [%0], %1;" :: "r"((uint32_t)(a)), "r"((uint32_t)(b)) : "memory")
#define MBAR_WAIT(a, ph) do {                                                        \
    uint32_t _m = (uint32_t)(a); uint32_t _p = (uint32_t)(ph); uint32_t _d;          \
    asm volatile("{\n\t.reg .pred p;\n\t"                                            \
        "mbarrier.try_wait.parity.acquire.cta.shared::cta.b64 p, [%1], %2;\n\t"      \
        "selp.b32 %0, 1, 0, p;\n\t}"                                                 \
        : "=r"(_d) : "r"(_m), "r"(_p) : "memory");                                   \
    if (!_d) {                                                                        \
        asm volatile("{\n\t.reg .pred P1;\n\t"                                       \
            "WL_%=:\n\t"                                                             \
            "mbarrier.try_wait.parity.acquire.cta.shared::cta.b64 P1, [%0], %1, 0x989680;\n\t" \
            "@P1 bra.uni WD_%=;\n\t"                                                 \
            "bra.uni WL_%=;\n\t"                                                     \
            "WD_%=:\n\t}"                                                            \
            :: "r"(_m), "r"(_p) : "memory");                                         \
    } } while (0)

#define BAR_SYNC(id, n)   asm volatile("bar.sync %0, %1;"   :: "r"(id), "r"(n) : "memory")
#define BAR_ARRIVE(id, n) asm volatile("bar.arrive %0, %1;" :: "r"(id), "r"(n) : "memory")

__device__ __forceinline__ uint32_t smem_u32(const void* p) {
    uint32_t a;
    asm("{ .reg .u64 t; cvta.to.shared.u64 t, %1; cvt.u32.u64 %0, t; }" : "=r"(a) : "l"(p));
    return a;
}

// ---------------- init ----------------
__global__ void init_kernel()
{
    int i = threadIdx.x;
    if (i < EE) { g_counts[i] = 0; g_probs_sum[i] = 0.f; }
}

// ---------------- unified prep: x conv + Wg/Wu pack + Wd pack ----------------
#define N8X  (TT * DD / 8)            // 262144
#define N8A  (NBLK * 4096)            // 2097152
#define N8B  (NBLK * 2048)            // 1048576
#define N8TOT (N8X + N8A + N8B)       // 3407872

__device__ __forceinline__ uint4 cvt8(const float* src) {
    float4 a = ((const float4*)src)[0];
    float4 b = ((const float4*)src)[1];
    __half2 h0 = __floats2half2_rn(a.x, a.y);
    __half2 h1 = __floats2half2_rn(a.z, a.w);
    __half2 h2 = __floats2half2_rn(b.x, b.y);
    __half2 h3 = __floats2half2_rn(b.z, b.w);
    uint4 o;
    o.x = *(uint32_t*)&h0; o.y = *(uint32_t*)&h1;
    o.z = *(uint32_t*)&h2; o.w = *(uint32_t*)&h3;
    return o;
}

__global__ __launch_bounds__(256) void prep_kernel(const float* __restrict__ x,
                                                   const float* __restrict__ wg,
                                                   const float* __restrict__ wu,
                                                   const float* __restrict__ wd)
{
    int gidx = blockIdx.x * 256 + threadIdx.x;
    if (gidx < N8X) {
        ((uint4*)g_xh)[gidx] = cvt8(x + (size_t)gidx * 8);
    } else if (gidx < N8X + N8A) {
        int idx = gidx - N8X;
        int blk = idx >> 12;
        int rem = idx & 4095;
        int ks  = rem >> 10;
        int mat = (rem >> 9) & 1;
        int f   = (rem >> 3) & 63;
        int k8  = rem & 7;
        int e = blk >> 4, c = blk & 15;
        const float* src = (mat ? wu : wg)
            + (((size_t)e * FF + (size_t)c * FC + f) * DD + ks * 64 + k8 * 8);
        __half* dst = g_wpack + ((size_t)blk * CHUNK_H + ks * SLICE_H + mat * (SLICE_H / 2)
                                 + f * 72 + k8 * 8);
        *(uint4*)dst = cvt8(src);
    } else if (gidx < N8TOT) {
        int idx = gidx - N8X - N8A;
        int blk = idx >> 11;
        int rem = idx & 2047;
        int q   = rem >> 9;
        int d   = (rem >> 3) & 63;
        int f8  = rem & 7;
        int e = blk >> 4, c = blk & 15;
        const float* src = wd + (((size_t)e * DD + q * 64 + d) * FF + (size_t)c * FC + f8 * 8);
        __half* dst = g_wpack + ((size_t)blk * CHUNK_H + APART_H + q * QUART_H
                                 + d * 72 + f8 * 8);
        *(uint4*)dst = cvt8(src);
    }
}

// ---------------- router (known-good) ----------------
__global__ __launch_bounds__(256) void router_kernel(const float* __restrict__ x,
                                                     const float* __restrict__ rw)
{
    __shared__ float rw_s[EE * 257];
    __shared__ float xsh[8 * 260];
    __shared__ float pacc[EE];

    const int tid  = threadIdx.x;
    const int lane = tid & 31;
    const int warp = tid >> 5;

    for (int i = tid; i < EE * DD; i += 256) {
        int e = i >> 8, d = i & 255;
        rw_s[e * 257 + d] = rw[i];
    }
    if (tid < EE) pacc[tid] = 0.f;
    __syncthreads();

    const int t = blockIdx.x * 8 + warp;
    {
        const float4* xr = (const float4*)(x + (size_t)t * DD);
        float4 a = xr[lane * 2];
        float4 b = xr[lane * 2 + 1];
        *(float4*)&xsh[warp * 260 + lane * 8]     = a;
        *(float4*)&xsh[warp * 260 + lane * 8 + 4] = b;
    }
    __syncwarp();

    float acc = 0.f;
    const float* xrow  = &xsh[warp * 260];
    const float* rwrow = &rw_s[lane * 257];
#pragma unroll 8
    for (int d = 0; d < DD; d++) acc = fmaf(xrow[d], rwrow[d], acc);
    const float logit = acc;

    float m = logit;
#pragma unroll
    for (int o = 16; o; o >>= 1) m = fmaxf(m, __shfl_xor_sync(0xffffffffu, m, o));
    float p = expf(logit - m);
    float s = p;
#pragma unroll
    for (int o = 16; o; o >>= 1) s += __shfl_xor_sync(0xffffffffu, s, o);
    atomicAdd(&pacc[lane], p / s);

    float lv = logit;
    float vals[KK]; int idxs[KK];
#pragma unroll
    for (int k = 0; k < KK; k++) {
        float v = lv; int id = lane;
#pragma unroll
        for (int o = 16; o; o >>= 1) {
            float v2 = __shfl_xor_sync(0xffffffffu, v, o);
            int   i2 = __shfl_xor_sync(0xffffffffu, id, o);
            if (v2 > v || (v2 == v && i2 < id)) { v = v2; id = i2; }
        }
        vals[k] = v; idxs[k] = id;
        if (lane == id) lv = __int_as_float(0xff800000);
    }

    float ws[KK]; float sum = 0.f;
#pragma unroll
    for (int k = 0; k < KK; k++) { ws[k] = expf(vals[k] - vals[0]); sum += ws[k]; }
    const float inv = 1.f / sum;

    if (lane == 0) {
#pragma unroll
        for (int k = 0; k < KK; k++) {
            int e   = idxs[k];
            int pos = atomicAdd(&g_counts[e], 1);
            int a   = t * KK + k;
            g_as_e[a] = e; g_as_pos[a] = pos; g_as_w[a] = ws[k] * inv;
        }
    }
    __syncthreads();
    if (tid < EE) atomicAdd(&g_probs_sum[tid], pacc[tid]);
}

// ---------------- scan offsets + aux loss + tile list ----------------
__global__ void scan_aux_kernel(float* __restrict__ out, int out_size)
{
    const int tid = threadIdx.x;   // 32 threads
    int c = g_counts[tid];
    int v = c;
#pragma unroll
    for (int o = 1; o < 32; o <<= 1) {
        int n = __shfl_up_sync(0xffffffffu, v, o);
        if (tid >= o) v += n;
    }
    g_offsets[tid] = v - c;
    if (tid == 31) g_offsets[EE] = v;

    int nt = (c + TM - 1) / TM;
    int tv = nt;
#pragma unroll
    for (int o = 1; o < 32; o <<= 1) {
        int n = __shfl_up_sync(0xffffffffu, tv, o);
        if (tid >= o) tv += n;
    }
    int tb = tv - nt;
    for (int j = 0; j < nt; j++) { g_tile_e[tb + j] = tid; g_tile_m0[tb + j] = j * TM; }
    if (tid == 31) g_ntiles = tv;

    const float invT = 1.f / (float)TT;
    float part = ((float)c * invT) * (g_probs_sum[tid] * invT);
#pragma unroll
    for (int o = 16; o; o >>= 1) part += __shfl_xor_sync(0xffffffffu, part, o);
    if (tid == 0 && out_size > TT * DD) out[(size_t)TT * DD] = (float)EE * part;
}

// ---------------- per-expert token lists + slot map ----------------
__global__ void fill_kernel()
{
    int i = blockIdx.x * blockDim.x + threadIdx.x;
    if (i < TT * KK) {
        int e    = g_as_e[i];
        int slot = g_offsets[e] + g_as_pos[i];
        g_list_tok[slot] = i >> 2;
        g_list_w[slot]   = g_as_w[i];
        g_slot[i]        = slot;
    }
}

// ---------------- fp16 mma.sync fused expert FFN ----------------
// SMEM layout (halves):
//   Xs  [128][264]   @ 0       (33792 h)
//   hS  [128][72]    @ 33792   (9216 h)
//   WA  [4][9216]    @ 43008   (36864 h)
//   WB  [4][4608]    @ 79872   (18432 h)
//   mbars @ 98304h (8 x 8B), toks @ 98336h, wsh after
constexpr int XS_STRIDE = 264;
constexpr int HS_STRIDE = 72;
constexpr int OFF_H    = 33792;
constexpr int OFF_WA   = 43008;
constexpr int OFF_WB   = 79872;
constexpr int OFF_MB   = 98304;
constexpr int OFF_TOK  = 98336;
constexpr int EXP_SMEM = (OFF_TOK + 520) * 2;   // 197712 B

__global__ __launch_bounds__(256, 1)
void moe_mma_kernel()
{
    extern __shared__ __half sm[];
    __half* Xs = sm;
    __half* hS = sm + OFF_H;
    int*   toks = (int*)(sm + OFF_TOK);
    float* wsh  = (float*)(toks + 128);

    const uint32_t xs_b = smem_u32(Xs);
    const uint32_t hs_b = smem_u32(hS);
    const uint32_t wa_b = smem_u32(sm + OFF_WA);
    const uint32_t wb_b = smem_u32(sm + OFF_WB);
    const uint32_t mb   = smem_u32(sm + OFF_MB);

    const int tid  = threadIdx.x;
    const int lane = tid & 31;
    const int warp = tid >> 5;
    const int lq   = lane & 3;
    const int lh   = lane >> 2;
    const int wm   = warp & 3;        // M tile (32 rows each)
    const int wn   = warp >> 2;       // N tile (32 cols each)

    const int l7  = lane & 7;
    const int l8  = (lane >> 3) & 1;
    const int l16 = (lane >> 4) & 1;

    const int rowA0 = wm * 32 + l7 + 8 * l8;
    const int rowB0 = wn * 32 + l7 + 8 * l8;

    const uint32_t aX = xs_b + (uint32_t)((rowA0 * XS_STRIDE + l16 * 8) * 2);
    const uint32_t aH = hs_b + (uint32_t)((rowA0 * HS_STRIDE + l16 * 8) * 2);
    const uint32_t bW = (uint32_t)((rowB0 * HS_STRIDE + l16 * 8) * 2);

    if (tid == 0) {
#pragma unroll
        for (int i = 0; i < 8; i++) MBARRIER_INIT(mb + i * 8, 1);
    }
    __syncthreads();

    int ph = 0;   // running parity: every barrier completes once per chunk
    bool first = true;

    const int ntiles = g_ntiles;

    for (int tile = blockIdx.x; tile < ntiles; tile += gridDim.x) {
        const int e     = g_tile_e[tile];
        const int m0    = g_tile_m0[tile];
        const int base  = g_offsets[e];
        const int count = g_offsets[e + 1] - base;

        if (tid < TM) {
            int r = m0 + tid;
            bool v = r < count;
            toks[tid] = v ? g_list_tok[base + r] : -1;
            wsh[tid]  = v ? g_list_w[base + r] : 0.f;
        }
        __syncthreads();

        const __half* wblk = g_wpack + (size_t)(e * NCH) * CHUNK_H;

        // very first tile of this CTA: prime chunk-0 copies
        if (first && tid == 0) {
#pragma unroll
            for (int s = 0; s < 4; s++) {
                MBARRIER_EXPECT_TX(mb + s * 8, SLICE_H * 2);
                bulk_g2s(wa_b + (uint32_t)(s * SLICE_H * 2),
                         wblk + (size_t)s * SLICE_H, SLICE_H * 2, mb + s * 8);
            }
#pragma unroll
            for (int q = 0; q < 4; q++) {
                MBARRIER_EXPECT_TX(mb + 32 + q * 8, QUART_H * 2);
                bulk_g2s(wb_b + (uint32_t)(q * QUART_H * 2),
                         wblk + APART_H + (size_t)q * QUART_H, QUART_H * 2, mb + 32 + q * 8);
            }
        }
        first = false;

        // ---- stage X fp16 (cp.async; once per tile) ----
#pragma unroll 4
        for (int j = 0; j < 16; j++) {
            int idx = tid + j * 256;
            int r = idx >> 5, c8 = idx & 31;
            int t = toks[r];
            uint32_t dst = xs_b + (uint32_t)((r * XS_STRIDE + c8 * 8) * 2);
            const __half* src = g_xh + ((size_t)(t < 0 ? 0 : t) * DD + c8 * 8);
            cp16z(dst, src, t < 0 ? 0 : 16);
        }
        CP_COMMIT();

        float acc[4][2][4][4];
#pragma unroll
        for (int q = 0; q < 4; q++)
#pragma unroll
            for (int mt = 0; mt < 2; mt++)
#pragma unroll
                for (int nt = 0; nt < 4; nt++)
#pragma unroll
                    for (int r = 0; r < 4; r++) acc[q][mt][nt][r] = 0.f;

        CP_WAIT0();
        __syncthreads();   // X visible

        for (int c = 0; c < NCH; c++) {
            // next weight block to prefetch (next chunk, or next tile's chunk 0)
            const __half* wnx;
            if (c < NCH - 1) {
                wnx = wblk + (size_t)(c + 1) * CHUNK_H;
            } else {
                int t2 = tile + gridDim.x;
                wnx = (t2 < ntiles)
                    ? g_wpack + (size_t)(g_tile_e[t2] * NCH) * CHUNK_H : (const __half*)0;
            }

            // ======== Phase A (fused G+U): 4 k-slices of 64 ========
            float cG[2][4][4], cU[2][4][4];
#pragma unroll
            for (int mt = 0; mt < 2; mt++)
#pragma unroll
                for (int nt = 0; nt < 4; nt++)
#pragma unroll
                    for (int r = 0; r < 4; r++) { cG[mt][nt][r] = 0.f; cU[mt][nt][r] = 0.f; }

#pragma unroll 1
            for (int ks = 0; ks < 4; ks++) {
                MBAR_WAIT(mb + ks * 8, ph);
                const uint32_t wsbB = wa_b + (uint32_t)(ks * SLICE_H * 2);
                const int d0 = ks * 64;
#pragma unroll
                for (int kk = 0; kk < 4; kk++) {
                    uint32_t a[2][4];
#pragma unroll
                    for (int mt = 0; mt < 2; mt++)
                        ldm4(a[mt], aX + (uint32_t)(((mt * 16 * XS_STRIDE) + d0 + kk * 16) * 2));
                    uint32_t bg[8], bu[8];
#pragma unroll
                    for (int nt2 = 0; nt2 < 2; nt2++) {
                        ldm4(bg + nt2 * 4, wsbB + bW + (uint32_t)(((nt2 * 16 * HS_STRIDE) + kk * 16) * 2));
                        ldm4(bu + nt2 * 4, wsbB + bW + (uint32_t)(((4608 + nt2 * 16 * HS_STRIDE) + kk * 16) * 2));
                    }
#pragma unroll
                    for (int mt = 0; mt < 2; mt++)
#pragma unroll
                        for (int nt = 0; nt < 4; nt++) {
                            int nt2 = nt >> 1, hi = nt & 1;
                            mma16(cG[mt][nt], a[mt], bg[nt2 * 4 + hi], bg[nt2 * 4 + 2 + hi]);
                            mma16(cU[mt][nt], a[mt], bu[nt2 * 4 + hi], bu[nt2 * 4 + 2 + hi]);
                        }
                }
            }

            // Phase A (incl. all WA reads) done for this warp
            if (warp != 0) BAR_ARRIVE(7, 256);

            // ---- h = silu(G) * U -> hS (fp16); sigmoid on MUFU pipe ----
#pragma unroll
            for (int mt = 0; mt < 2; mt++)
#pragma unroll
                for (int nt = 0; nt < 4; nt++) {
                    int col = wn * 32 + nt * 8 + 2 * lq;
#pragma unroll
                    for (int hf = 0; hf < 2; hf++) {
                        int row = wm * 32 + mt * 16 + hf * 8 + lh;
                        float g0 = cG[mt][nt][hf * 2 + 0];
                        float g1 = cG[mt][nt][hf * 2 + 1];
                        float s0 = __fdividef(g0, 1.f + __expf(-g0));
                        float s1 = __fdividef(g1, 1.f + __expf(-g1));
                        float h0 = s0 * cU[mt][nt][hf * 2 + 0];
                        float h1 = s1 * cU[mt][nt][hf * 2 + 1];
                        __half2 o2 = __floats2half2_rn(h0, h1);
                        *(__half2*)&hS[row * HS_STRIDE + col] = o2;
                    }
                }

            // hS handoff within row-group wm only (warps wm and wm+4)
            BAR_SYNC(1 + wm, 64);

            // warp 0: wait for all Phase A reads, then rearm WA (Phase-B lead)
            if (warp == 0) {
                BAR_SYNC(7, 256);   // own arrival counts; others arrived pre-silu
                if (wnx && tid == 0) {
#pragma unroll
                    for (int s = 0; s < 4; s++) {
                        MBARRIER_EXPECT_TX(mb + s * 8, SLICE_H * 2);
                        bulk_g2s(wa_b + (uint32_t)(s * SLICE_H * 2),
                                 wnx + (size_t)s * SLICE_H, SLICE_H * 2, mb + s * 8);
                    }
                }
            }

            // ======== Phase B: out += h @ Wd^T (4 quarters of D) ========
#pragma unroll 1
            for (int q = 0; q < 4; q++) {
                MBAR_WAIT(mb + 32 + q * 8, ph);
                const uint32_t wdbB = wb_b + (uint32_t)(q * QUART_H * 2);
#pragma unroll
                for (int kk = 0; kk < 4; kk++) {
                    uint32_t a[2][4];
#pragma unroll
                    for (int mt = 0; mt < 2; mt++)
                        ldm4(a[mt], aH + (uint32_t)(((mt * 16 * HS_STRIDE) + kk * 16) * 2));
                    uint32_t bbr[8];
#pragma unroll
                    for (int nt2 = 0; nt2 < 2; nt2++)
                        ldm4(bbr + nt2 * 4, wdbB + bW + (uint32_t)(((nt2 * 16 * HS_STRIDE) + kk * 16) * 2));
#pragma unroll
                    for (int mt = 0; mt < 2; mt++)
#pragma unroll
                        for (int nt = 0; nt < 4; nt++) {
                            int nt2 = nt >> 1, hi = nt & 1;
                            mma16(acc[q][mt][nt], a[mt], bbr[nt2 * 4 + hi], bbr[nt2 * 4 + 2 + hi]);
                        }
                }
            }

            __syncthreads();   // chunk end: WB/hS reads complete everywhere
            ph ^= 1;

            // rearm WB quarters — overlaps next Phase A (or epilogue)
            if (wnx && tid == 0) {
#pragma unroll
                for (int q = 0; q < 4; q++) {
                    MBARRIER_EXPECT_TX(mb + 32 + q * 8, QUART_H * 2);
                    bulk_g2s(wb_b + (uint32_t)(q * QUART_H * 2),
                             wnx + APART_H + (size_t)q * QUART_H, QUART_H * 2, mb + 32 + q * 8);
                }
            }
        }

        // ---- epilogue: weighted write to scratch ----
#pragma unroll
        for (int q = 0; q < 4; q++)
#pragma unroll
            for (int mt = 0; mt < 2; mt++)
#pragma unroll
                for (int hf = 0; hf < 2; hf++) {
                    int tr = wm * 32 + mt * 16 + hf * 8 + lh;
                    if (m0 + tr < count) {
                        float w = wsh[tr];
                        float* dst = g_scratch + (size_t)(base + m0 + tr) * DD
                                   + q * 64 + wn * 32 + 2 * lq;
#pragma unroll
                        for (int nt = 0; nt < 4; nt++) {
                            float2 v;
                            v.x = acc[q][mt][nt][hf * 2 + 0] * w;
                            v.y = acc[q][mt][nt][hf * 2 + 1] * w;
                            *(float2*)(dst + nt * 8) = v;
                        }
                    }
                }
        __syncthreads();   // protect toks/wsh/Xs before next tile
    }
}

// ---------------- combine: out[t] = sum of token's 4 weighted slots ----------------
__global__ __launch_bounds__(256) void combine_kernel(float* __restrict__ out)
{
    int idx = blockIdx.x * 256 + threadIdx.x;     // TT*64 float4 items
    int t = idx >> 6, q = (idx & 63) * 4;
    const int* sl = g_slot + t * 4;
    float4 a = *(const float4*)(g_scratch + (size_t)sl[0] * DD + q);
    float4 b = *(const float4*)(g_scratch + (size_t)sl[1] * DD + q);
    float4 c = *(const float4*)(g_scratch + (size_t)sl[2] * DD + q);
    float4 d = *(const float4*)(g_scratch + (size_t)sl[3] * DD + q);
    float4 r;
    r.x = a.x + b.x + c.x + d.x;
    r.y = a.y + b.y + c.y + d.y;
    r.z = a.z + b.z + c.z + d.z;
    r.w = a.w + b.w + c.w + d.w;
    *(float4*)(out + (size_t)t * DD + q) = r;
}

// ---------------- launch ----------------
extern "C" void kernel_launch(void* const* d_in, const int* in_sizes, int n_in,
                              void* d_out, int out_size)
{
    const float* x  = (const float*)d_in[0];
    const float* rw = (const float*)d_in[1];
    const float* wg = (const float*)d_in[2];
    const float* wu = (const float*)d_in[3];
    const float* wd = (const float*)d_in[4];
    float* out = (float*)d_out;

    // combine writes [0, TT*DD); scan writes the aux slot. Clear only padding tail.
    if (out_size > TT * DD)
        cudaMemsetAsync((char*)d_out + (size_t)TT * DD * sizeof(float), 0,
                        ((size_t)out_size - TT * DD) * sizeof(float));

    init_kernel<<<1, 32>>>();
    router_kernel<<<TT / 8, 256>>>(x, rw);
    scan_aux_kernel<<<1, 32>>>(out, out_size);
    fill_kernel<<<(TT * KK + 255) / 256, 256>>>();

    prep_kernel<<<(N8TOT + 255) / 256, 256>>>(x, wg, wu, wd);

    cudaFuncSetAttribute(moe_mma_kernel,
                         cudaFuncAttributeMaxDynamicSharedMemorySize, EXP_SMEM);
    moe_mma_kernel<<<148, 256, EXP_SMEM>>>();
    combine_kernel<<<TT * 64 / 256, 256>>>(out);
}

// round 16
// speedup vs baseline: 1.2424x; 1.0193x over previous
#include <cuda_runtime.h>
#include <cuda_fp16.h>
#include <math.h>
#include <stdint.h>

#define TT 8192
#define DD 256
#define FF 1024
#define EE 32
#define KK 4
#define TM 128            // tokens per tile (MMA M)
#define FC 64             // ffn chunk
#define NCH (FF / FC)     // 16

// packed-weight block geometry (halves)
#define SLICE_H  9216     // [2 mat][64 f][72]
#define QUART_H  4608     // [64 d][72]
#define APART_H  (4 * SLICE_H)            // 36864
#define CHUNK_H  (APART_H + 4 * QUART_H)  // 55296
#define NBLK     (EE * NCH)               // 512

// ---------------- scratch globals ----------------
__device__ int   g_counts[EE];
__device__ int   g_offsets[EE + 1];
__device__ float g_probs_sum[EE];
__device__ int   g_as_e[TT * KK];
__device__ int   g_as_pos[TT * KK];
__device__ float g_as_w[TT * KK];
__device__ int   g_list_tok[TT * KK];
__device__ float g_list_w[TT * KK];
__device__ int   g_slot[TT * KK];
__device__ int   g_tile_e[2048];
__device__ int   g_tile_m0[2048];
__device__ int   g_ntiles;
__device__ float g_scratch[(size_t)TT * KK * DD];       // 32 MB partials
__device__ __half g_xh[(size_t)TT * DD];                // 4 MB fp16 x
__device__ __half g_wpack[(size_t)NBLK * CHUNK_H];      // 56.6 MB packed weights

// ---------------- PTX helpers ----------------
__device__ __forceinline__ void mma16(float* c, const uint32_t* a, uint32_t b0, uint32_t b1) {
    asm("mma.sync.aligned.m16n8k16.row.col.f32.f16.f16.f32 "
        "{%0,%1,%2,%3},{%4,%5,%6,%7},{%8,%9},{%0,%1,%2,%3};"
        : "+f"(c[0]), "+f"(c[1]), "+f"(c[2]), "+f"(c[3])
        : "r"(a[0]), "r"(a[1]), "r"(a[2]), "r"(a[3]), "r"(b0), "r"(b1));
}
__device__ __forceinline__ void ldm4(uint32_t* r, uint32_t addr) {
    asm volatile("ldmatrix.sync.aligned.m8n8.x4.shared.b16 {%0,%1,%2,%3}, [%4];"
        : "=r"(r[0]), "=r"(r[1]), "=r"(r[2]), "=r"(r[3]) : "r"(addr));
}
__device__ __forceinline__ void cp16z(uint32_t dst, const void* src, int ssz) {
    asm volatile("cp.async.cg.shared.global [%0], [%1], 16, %2;" :: "r"(dst), "l"(src), "r"(ssz));
}
#define CP_COMMIT() asm volatile("cp.async.commit_group;" ::: "memory")
#define CP_WAIT0()  asm volatile("cp.async.wait_group 0;" ::: "memory")

__device__ __forceinline__ void bulk_g2s(uint32_t dst, const void* src, uint32_t bytes,
                                         uint32_t mbar) {
    asm volatile("cp.async.bulk.shared::cta.global.mbarrier::complete_tx::bytes "
                 "[%0], [%1], %2, [%3];"
                 :: "r"(dst), "l"(src), "r"(bytes), "r"(mbar) : "memory");
}
#define MBARRIER_INIT(a, n) \
    asm volatile("mbarrier.init.shared.b64 [%0], %1;" :: "r"((uint32_t)(a)), "r"((uint32_t)(n)) : "memory")
#define MBARRIER_EXPECT_TX(a, b) \
    asm volatile("mbarrier.arrive.expect_tx.shared.b64 _, [%0], %1;" :: "r"((uint32_t)(a)), "r"((uint32_t)(b)) : "memory")
#define MBAR_WAIT(a, ph) do {                                                        \
    uint32_t _m = (uint32_t)(a); uint32_t _p = (uint32_t)(ph); uint32_t _d;          \
    asm volatile("{\n\t.reg .pred p;\n\t"                                            \
        "mbarrier.try_wait.parity.acquire.cta.shared::cta.b64 p, [%1], %2;\n\t"      \
        "selp.b32 %0, 1, 0, p;\n\t}"                                                 \
        : "=r"(_d) : "r"(_m), "r"(_p) : "memory");                                   \
    if (!_d) {                                                                        \
        asm volatile("{\n\t.reg .pred P1;\n\t"                                       \
            "WL_%=:\n\t"                                                             \
            "mbarrier.try_wait.parity.acquire.cta.shared::cta.b64 P1, [%0], %1, 0x989680;\n\t" \
            "@P1 bra.uni WD_%=;\n\t"                                                 \
            "bra.uni WL_%=;\n\t"                                                     \
            "WD_%=:\n\t}"                                                            \
            :: "r"(_m), "r"(_p) : "memory");                                         \
    } } while (0)

#define BAR_SYNC(id, n)   asm volatile("bar.sync %0, %1;"   :: "r"(id), "r"(n) : "memory")
#define BAR_ARRIVE(id, n) asm volatile("bar.arrive %0, %1;" :: "r"(id), "r"(n) : "memory")

__device__ __forceinline__ uint32_t smem_u32(const void* p) {
    uint32_t a;
    asm("{ .reg .u64 t; cvta.to.shared.u64 t, %1; cvt.u32.u64 %0, t; }" : "=r"(a) : "l"(p));
    return a;
}

// ---------------- init ----------------
__global__ void init_kernel()
{
    int i = threadIdx.x;
    if (i < EE) { g_counts[i] = 0; g_probs_sum[i] = 0.f; }
}

// ---------------- unified prep: x conv + Wg/Wu pack + Wd pack ----------------
#define N8X  (TT * DD / 8)            // 262144
#define N8A  (NBLK * 4096)            // 2097152
#define N8B  (NBLK * 2048)            // 1048576
#define N8TOT (N8X + N8A + N8B)       // 3407872

__device__ __forceinline__ uint4 cvt8(const float* src) {
    float4 a = ((const float4*)src)[0];
    float4 b = ((const float4*)src)[1];
    __half2 h0 = __floats2half2_rn(a.x, a.y);
    __half2 h1 = __floats2half2_rn(a.z, a.w);
    __half2 h2 = __floats2half2_rn(b.x, b.y);
    __half2 h3 = __floats2half2_rn(b.z, b.w);
    uint4 o;
    o.x = *(uint32_t*)&h0; o.y = *(uint32_t*)&h1;
    o.z = *(uint32_t*)&h2; o.w = *(uint32_t*)&h3;
    return o;
}

__global__ __launch_bounds__(256) void prep_kernel(const float* __restrict__ x,
                                                   const float* __restrict__ wg,
                                                   const float* __restrict__ wu,
                                                   const float* __restrict__ wd)
{
    int gidx = blockIdx.x * 256 + threadIdx.x;
    if (gidx < N8X) {
        ((uint4*)g_xh)[gidx] = cvt8(x + (size_t)gidx * 8);
    } else if (gidx < N8X + N8A) {
        int idx = gidx - N8X;
        int blk = idx >> 12;
        int rem = idx & 4095;
        int ks  = rem >> 10;
        int mat = (rem >> 9) & 1;
        int f   = (rem >> 3) & 63;
        int k8  = rem & 7;
        int e = blk >> 4, c = blk & 15;
        const float* src = (mat ? wu : wg)
            + (((size_t)e * FF + (size_t)c * FC + f) * DD + ks * 64 + k8 * 8);
        __half* dst = g_wpack + ((size_t)blk * CHUNK_H + ks * SLICE_H + mat * (SLICE_H / 2)
                                 + f * 72 + k8 * 8);
        *(uint4*)dst = cvt8(src);
    } else if (gidx < N8TOT) {
        int idx = gidx - N8X - N8A;
        int blk = idx >> 11;
        int rem = idx & 2047;
        int q   = rem >> 9;
        int d   = (rem >> 3) & 63;
        int f8  = rem & 7;
        int e = blk >> 4, c = blk & 15;
        const float* src = wd + (((size_t)e * DD + q * 64 + d) * FF + (size_t)c * FC + f8 * 8);
        __half* dst = g_wpack + ((size_t)blk * CHUNK_H + APART_H + q * QUART_H
                                 + d * 72 + f8 * 8);
        *(uint4*)dst = cvt8(src);
    }
}

// ---------------- router (known-good) ----------------
__global__ __launch_bounds__(256) void router_kernel(const float* __restrict__ x,
                                                     const float* __restrict__ rw)
{
    __shared__ float rw_s[EE * 257];
    __shared__ float xsh[8 * 260];
    __shared__ float pacc[EE];

    const int tid  = threadIdx.x;
    const int lane = tid & 31;
    const int warp = tid >> 5;

    for (int i = tid; i < EE * DD; i += 256) {
        int e = i >> 8, d = i & 255;
        rw_s[e * 257 + d] = rw[i];
    }
    if (tid < EE) pacc[tid] = 0.f;
    __syncthreads();

    const int t = blockIdx.x * 8 + warp;
    {
        const float4* xr = (const float4*)(x + (size_t)t * DD);
        float4 a = xr[lane * 2];
        float4 b = xr[lane * 2 + 1];
        *(float4*)&xsh[warp * 260 + lane * 8]     = a;
        *(float4*)&xsh[warp * 260 + lane * 8 + 4] = b;
    }
    __syncwarp();

    float acc = 0.f;
    const float* xrow  = &xsh[warp * 260];
    const float* rwrow = &rw_s[lane * 257];
#pragma unroll 8
    for (int d = 0; d < DD; d++) acc = fmaf(xrow[d], rwrow[d], acc);
    const float logit = acc;

    float m = logit;
#pragma unroll
    for (int o = 16; o; o >>= 1) m = fmaxf(m, __shfl_xor_sync(0xffffffffu, m, o));
    float p = expf(logit - m);
    float s = p;
#pragma unroll
    for (int o = 16; o; o >>= 1) s += __shfl_xor_sync(0xffffffffu, s, o);
    atomicAdd(&pacc[lane], p / s);

    float lv = logit;
    float vals[KK]; int idxs[KK];
#pragma unroll
    for (int k = 0; k < KK; k++) {
        float v = lv; int id = lane;
#pragma unroll
        for (int o = 16; o; o >>= 1) {
            float v2 = __shfl_xor_sync(0xffffffffu, v, o);
            int   i2 = __shfl_xor_sync(0xffffffffu, id, o);
            if (v2 > v || (v2 == v && i2 < id)) { v = v2; id = i2; }
        }
        vals[k] = v; idxs[k] = id;
        if (lane == id) lv = __int_as_float(0xff800000);
    }

    float ws[KK]; float sum = 0.f;
#pragma unroll
    for (int k = 0; k < KK; k++) { ws[k] = expf(vals[k] - vals[0]); sum += ws[k]; }
    const float inv = 1.f / sum;

    if (lane == 0) {
#pragma unroll
        for (int k = 0; k < KK; k++) {
            int e   = idxs[k];
            int pos = atomicAdd(&g_counts[e], 1);
            int a   = t * KK + k;
            g_as_e[a] = e; g_as_pos[a] = pos; g_as_w[a] = ws[k] * inv;
        }
    }
    __syncthreads();
    if (tid < EE) atomicAdd(&g_probs_sum[tid], pacc[tid]);
}

// ---------------- scan offsets + aux loss + tile list ----------------
__global__ void scan_aux_kernel(float* __restrict__ out, int out_size)
{
    const int tid = threadIdx.x;   // 32 threads
    int c = g_counts[tid];
    int v = c;
#pragma unroll
    for (int o = 1; o < 32; o <<= 1) {
        int n = __shfl_up_sync(0xffffffffu, v, o);
        if (tid >= o) v += n;
    }
    g_offsets[tid] = v - c;
    if (tid == 31) g_offsets[EE] = v;

    int nt = (c + TM - 1) / TM;
    int tv = nt;
#pragma unroll
    for (int o = 1; o < 32; o <<= 1) {
        int n = __shfl_up_sync(0xffffffffu, tv, o);
        if (tid >= o) tv += n;
    }
    int tb = tv - nt;
    for (int j = 0; j < nt; j++) { g_tile_e[tb + j] = tid; g_tile_m0[tb + j] = j * TM; }
    if (tid == 31) g_ntiles = tv;

    const float invT = 1.f / (float)TT;
    float part = ((float)c * invT) * (g_probs_sum[tid] * invT);
#pragma unroll
    for (int o = 16; o; o >>= 1) part += __shfl_xor_sync(0xffffffffu, part, o);
    if (tid == 0 && out_size > TT * DD) out[(size_t)TT * DD] = (float)EE * part;
}

// ---------------- per-expert token lists + slot map ----------------
__global__ void fill_kernel()
{
    int i = blockIdx.x * blockDim.x + threadIdx.x;
    if (i < TT * KK) {
        int e    = g_as_e[i];
        int slot = g_offsets[e] + g_as_pos[i];
        g_list_tok[slot] = i >> 2;
        g_list_w[slot]   = g_as_w[i];
        g_slot[i]        = slot;
    }
}

// ---------------- fp16 mma.sync fused expert FFN ----------------
// SMEM layout (halves):
//   Xs  [128][264]   @ 0       (33792 h)
//   hS  [128][72]    @ 33792   (9216 h)
//   WA  [4][9216]    @ 43008   (36864 h)
//   WB  [4][4608]    @ 79872   (18432 h)
//   mbars @ 98304h (8 x 8B), toks @ 98336h, wsh after
constexpr int XS_STRIDE = 264;
constexpr int HS_STRIDE = 72;
constexpr int OFF_H    = 33792;
constexpr int OFF_WA   = 43008;
constexpr int OFF_WB   = 79872;
constexpr int OFF_MB   = 98304;
constexpr int OFF_TOK  = 98336;
constexpr int EXP_SMEM = (OFF_TOK + 520) * 2;   // 197712 B

__global__ __launch_bounds__(256, 1)
void moe_mma_kernel()
{
    extern __shared__ __half sm[];
    __half* Xs = sm;
    __half* hS = sm + OFF_H;
    int*   toks = (int*)(sm + OFF_TOK);
    float* wsh  = (float*)(toks + 128);

    const uint32_t xs_b = smem_u32(Xs);
    const uint32_t hs_b = smem_u32(hS);
    const uint32_t wa_b = smem_u32(sm + OFF_WA);
    const uint32_t wb_b = smem_u32(sm + OFF_WB);
    const uint32_t mb   = smem_u32(sm + OFF_MB);

    const int tid  = threadIdx.x;
    const int lane = tid & 31;
    const int warp = tid >> 5;
    const int lq   = lane & 3;
    const int lh   = lane >> 2;
    const int wm   = warp & 3;        // M tile (32 rows each)
    const int wn   = warp >> 2;       // N tile (32 cols each)

    const int l7  = lane & 7;
    const int l8  = (lane >> 3) & 1;
    const int l16 = (lane >> 4) & 1;

    const int rowA0 = wm * 32 + l7 + 8 * l8;
    const int rowB0 = wn * 32 + l7 + 8 * l8;

    const uint32_t aX = xs_b + (uint32_t)((rowA0 * XS_STRIDE + l16 * 8) * 2);
    const uint32_t aH = hs_b + (uint32_t)((rowA0 * HS_STRIDE + l16 * 8) * 2);
    const uint32_t bW = (uint32_t)((rowB0 * HS_STRIDE + l16 * 8) * 2);

    if (tid == 0) {
#pragma unroll
        for (int i = 0; i < 8; i++) MBARRIER_INIT(mb + i * 8, 1);
    }
    __syncthreads();

    int ph = 0;   // running parity: every barrier completes once per chunk
    bool first = true;

    const int ntiles = g_ntiles;

    for (int tile = blockIdx.x; tile < ntiles; tile += gridDim.x) {
        const int e     = g_tile_e[tile];
        const int m0    = g_tile_m0[tile];
        const int base  = g_offsets[e];
        const int count = g_offsets[e + 1] - base;

        if (tid < TM) {
            int r = m0 + tid;
            bool v = r < count;
            toks[tid] = v ? g_list_tok[base + r] : -1;
            wsh[tid]  = v ? g_list_w[base + r] : 0.f;
        }
        __syncthreads();

        const __half* wblk = g_wpack + (size_t)(e * NCH) * CHUNK_H;

        // very first tile of this CTA: prime chunk-0 copies
        if (first && tid == 0) {
#pragma unroll
            for (int s = 0; s < 4; s++) {
                MBARRIER_EXPECT_TX(mb + s * 8, SLICE_H * 2);
                bulk_g2s(wa_b + (uint32_t)(s * SLICE_H * 2),
                         wblk + (size_t)s * SLICE_H, SLICE_H * 2, mb + s * 8);
            }
#pragma unroll
            for (int q = 0; q < 4; q++) {
                MBARRIER_EXPECT_TX(mb + 32 + q * 8, QUART_H * 2);
                bulk_g2s(wb_b + (uint32_t)(q * QUART_H * 2),
                         wblk + APART_H + (size_t)q * QUART_H, QUART_H * 2, mb + 32 + q * 8);
            }
        }
        first = false;

        // ---- stage X fp16 (cp.async; once per tile) ----
#pragma unroll 4
        for (int j = 0; j < 16; j++) {
            int idx = tid + j * 256;
            int r = idx >> 5, c8 = idx & 31;
            int t = toks[r];
            uint32_t dst = xs_b + (uint32_t)((r * XS_STRIDE + c8 * 8) * 2);
            const __half* src = g_xh + ((size_t)(t < 0 ? 0 : t) * DD + c8 * 8);
            cp16z(dst, src, t < 0 ? 0 : 16);
        }
        CP_COMMIT();

        float acc[4][2][4][4];
#pragma unroll
        for (int q = 0; q < 4; q++)
#pragma unroll
            for (int mt = 0; mt < 2; mt++)
#pragma unroll
                for (int nt = 0; nt < 4; nt++)
#pragma unroll
                    for (int r = 0; r < 4; r++) acc[q][mt][nt][r] = 0.f;

        CP_WAIT0();
        __syncthreads();   // X visible

        for (int c = 0; c < NCH; c++) {
            // next weight block to prefetch (next chunk, or next tile's chunk 0)
            const __half* wnx;
            if (c < NCH - 1) {
                wnx = wblk + (size_t)(c + 1) * CHUNK_H;
            } else {
                int t2 = tile + gridDim.x;
                wnx = (t2 < ntiles)
                    ? g_wpack + (size_t)(g_tile_e[t2] * NCH) * CHUNK_H : (const __half*)0;
            }

            // ======== Phase A (fused G+U): 4 k-slices of 64 ========
            float cG[2][4][4], cU[2][4][4];
#pragma unroll
            for (int mt = 0; mt < 2; mt++)
#pragma unroll
                for (int nt = 0; nt < 4; nt++)
#pragma unroll
                    for (int r = 0; r < 4; r++) { cG[mt][nt][r] = 0.f; cU[mt][nt][r] = 0.f; }

#pragma unroll 1
            for (int ks = 0; ks < 4; ks++) {
                MBAR_WAIT(mb + ks * 8, ph);
                const uint32_t wsbB = wa_b + (uint32_t)(ks * SLICE_H * 2);
                const int d0 = ks * 64;
#pragma unroll
                for (int kk = 0; kk < 4; kk++) {
                    uint32_t a[2][4];
#pragma unroll
                    for (int mt = 0; mt < 2; mt++)
                        ldm4(a[mt], aX + (uint32_t)(((mt * 16 * XS_STRIDE) + d0 + kk * 16) * 2));
                    uint32_t bg[8], bu[8];
#pragma unroll
                    for (int nt2 = 0; nt2 < 2; nt2++) {
                        ldm4(bg + nt2 * 4, wsbB + bW + (uint32_t)(((nt2 * 16 * HS_STRIDE) + kk * 16) * 2));
                        ldm4(bu + nt2 * 4, wsbB + bW + (uint32_t)(((4608 + nt2 * 16 * HS_STRIDE) + kk * 16) * 2));
                    }
#pragma unroll
                    for (int mt = 0; mt < 2; mt++)
#pragma unroll
                        for (int nt = 0; nt < 4; nt++) {
                            int nt2 = nt >> 1, hi = nt & 1;
                            mma16(cG[mt][nt], a[mt], bg[nt2 * 4 + hi], bg[nt2 * 4 + 2 + hi]);
                            mma16(cU[mt][nt], a[mt], bu[nt2 * 4 + hi], bu[nt2 * 4 + 2 + hi]);
                        }
                }
            }

            // Phase A (incl. all WA reads) done for this warp
            if (warp != 0) BAR_ARRIVE(7, 256);

            // ---- h = silu(G) * U -> hS (fp16); sigmoid on MUFU pipe ----
#pragma unroll
            for (int mt = 0; mt < 2; mt++)
#pragma unroll
                for (int nt = 0; nt < 4; nt++) {
                    int col = wn * 32 + nt * 8 + 2 * lq;
#pragma unroll
                    for (int hf = 0; hf < 2; hf++) {
                        int row = wm * 32 + mt * 16 + hf * 8 + lh;
                        float g0 = cG[mt][nt][hf * 2 + 0];
                        float g1 = cG[mt][nt][hf * 2 + 1];
                        float s0 = __fdividef(g0, 1.f + __expf(-g0));
                        float s1 = __fdividef(g1, 1.f + __expf(-g1));
                        float h0 = s0 * cU[mt][nt][hf * 2 + 0];
                        float h1 = s1 * cU[mt][nt][hf * 2 + 1];
                        __half2 o2 = __floats2half2_rn(h0, h1);
                        *(__half2*)&hS[row * HS_STRIDE + col] = o2;
                    }
                }

            // hS handoff within row-group wm only (warps wm and wm+4)
            BAR_SYNC(1 + wm, 64);

            // warp 0: wait for all Phase A reads, then rearm WA (Phase-B lead)
            if (warp == 0) {
                BAR_SYNC(7, 256);   // own arrival counts; others arrived pre-silu
                if (wnx && tid == 0) {
#pragma unroll
                    for (int s = 0; s < 4; s++) {
                        MBARRIER_EXPECT_TX(mb + s * 8, SLICE_H * 2);
                        bulk_g2s(wa_b + (uint32_t)(s * SLICE_H * 2),
                                 wnx + (size_t)s * SLICE_H, SLICE_H * 2, mb + s * 8);
                    }
                }
            }

            // ======== Phase B: out += h @ Wd^T (4 quarters of D) ========
#pragma unroll 1
            for (int q = 0; q < 4; q++) {
                MBAR_WAIT(mb + 32 + q * 8, ph);
                const uint32_t wdbB = wb_b + (uint32_t)(q * QUART_H * 2);
#pragma unroll
                for (int kk = 0; kk < 4; kk++) {
                    uint32_t a[2][4];
#pragma unroll
                    for (int mt = 0; mt < 2; mt++)
                        ldm4(a[mt], aH + (uint32_t)(((mt * 16 * HS_STRIDE) + kk * 16) * 2));
                    uint32_t bbr[8];
#pragma unroll
                    for (int nt2 = 0; nt2 < 2; nt2++)
                        ldm4(bbr + nt2 * 4, wdbB + bW + (uint32_t)(((nt2 * 16 * HS_STRIDE) + kk * 16) * 2));
#pragma unroll
                    for (int mt = 0; mt < 2; mt++)
#pragma unroll
                        for (int nt = 0; nt < 4; nt++) {
                            int nt2 = nt >> 1, hi = nt & 1;
                            mma16(acc[q][mt][nt], a[mt], bbr[nt2 * 4 + hi], bbr[nt2 * 4 + 2 + hi]);
                        }
                }
            }

            __syncthreads();   // chunk end: WB/hS reads complete everywhere
            ph ^= 1;

            // rearm WB quarters — overlaps next Phase A (or epilogue)
            if (wnx && tid == 0) {
#pragma unroll
                for (int q = 0; q < 4; q++) {
                    MBARRIER_EXPECT_TX(mb + 32 + q * 8, QUART_H * 2);
                    bulk_g2s(wb_b + (uint32_t)(q * QUART_H * 2),
                             wnx + APART_H + (size_t)q * QUART_H, QUART_H * 2, mb + 32 + q * 8);
                }
            }
        }

        // ---- epilogue: weighted write to scratch ----
#pragma unroll
        for (int q = 0; q < 4; q++)
#pragma unroll
            for (int mt = 0; mt < 2; mt++)
#pragma unroll
                for (int hf = 0; hf < 2; hf++) {
                    int tr = wm * 32 + mt * 16 + hf * 8 + lh;
                    if (m0 + tr < count) {
                        float w = wsh[tr];
                        float* dst = g_scratch + (size_t)(base + m0 + tr) * DD
                                   + q * 64 + wn * 32 + 2 * lq;
#pragma unroll
                        for (int nt = 0; nt < 4; nt++) {
                            float2 v;
                            v.x = acc[q][mt][nt][hf * 2 + 0] * w;
                            v.y = acc[q][mt][nt][hf * 2 + 1] * w;
                            *(float2*)(dst + nt * 8) = v;
                        }
                    }
                }
        __syncthreads();   // protect toks/wsh/Xs before next tile
    }
}

// ---------------- combine: out[t] = sum of token's 4 weighted slots ----------------
__global__ __launch_bounds__(256) void combine_kernel(float* __restrict__ out)
{
    int idx = blockIdx.x * 256 + threadIdx.x;     // TT*64 float4 items
    int t = idx >> 6, q = (idx & 63) * 4;
    const int* sl = g_slot + t * 4;
    float4 a = *(const float4*)(g_scratch + (size_t)sl[0] * DD + q);
    float4 b = *(const float4*)(g_scratch + (size_t)sl[1] * DD + q);
    float4 c = *(const float4*)(g_scratch + (size_t)sl[2] * DD + q);
    float4 d = *(const float4*)(g_scratch + (size_t)sl[3] * DD + q);
    float4 r;
    r.x = a.x + b.x + c.x + d.x;
    r.y = a.y + b.y + c.y + d.y;
    r.z = a.z + b.z + c.z + d.z;
    r.w = a.w + b.w + c.w + d.w;
    *(float4*)(out + (size_t)t * DD + q) = r;
}

// ---------------- launch ----------------
extern "C" void kernel_launch(void* const* d_in, const int* in_sizes, int n_in,
                              void* d_out, int out_size)
{
    const float* x  = (const float*)d_in[0];
    const float* rw = (const float*)d_in[1];
    const float* wg = (const float*)d_in[2];
    const float* wu = (const float*)d_in[3];
    const float* wd = (const float*)d_in[4];
    float* out = (float*)d_out;

    // lazily-created side stream + fork/join events (created on the first,
    // non-captured correctness call; same captured work every call thereafter)
    static cudaStream_t s_side = nullptr;
    static cudaEvent_t  s_fork = nullptr, s_join = nullptr;
    if (!s_side) {
        cudaStreamCreateWithFlags(&s_side, cudaStreamNonBlocking);
        cudaEventCreateWithFlags(&s_fork, cudaEventDisableTiming);
        cudaEventCreateWithFlags(&s_join, cudaEventDisableTiming);
        cudaFuncSetAttribute(moe_mma_kernel,
                             cudaFuncAttributeMaxDynamicSharedMemorySize, EXP_SMEM);
    }

    // combine writes [0, TT*DD); scan writes the aux slot. Clear only padding tail.
    if (out_size > TT * DD)
        cudaMemsetAsync((char*)d_out + (size_t)TT * DD * sizeof(float), 0,
                        ((size_t)out_size - TT * DD) * sizeof(float));

    // fork: prep (fp16 convert + weight pack) runs concurrently with router chain
    cudaEventRecord(s_fork, 0);
    cudaStreamWaitEvent(s_side, s_fork, 0);
    prep_kernel<<<(N8TOT + 255) / 256, 256, 0, s_side>>>(x, wg, wu, wd);
    cudaEventRecord(s_join, s_side);

    // main chain: routing
    init_kernel<<<1, 32>>>();
    router_kernel<<<TT / 8, 256>>>(x, rw);
    scan_aux_kernel<<<1, 32>>>(out, out_size);
    fill_kernel<<<(TT * KK + 255) / 256, 256>>>();

    // join: expert kernel needs both tile lists and packed weights
    cudaStreamWaitEvent(0, s_join, 0);

    moe_mma_kernel<<<148, 256, EXP_SMEM>>>();
    combine_kernel<<<TT * 64 / 256, 256>>>(out);
}